// round 6
// baseline (speedup 1.0000x reference)
#include <cuda_runtime.h>
#include <cuda_bf16.h>

#define DD   768
#define BB   8
#define SS   2048
#define MTOT (BB * SS)
#define BK   64
#define PITCH 40                         // bf16 per smem row (80B, conflict-free)
#define HALF_BYTES  (128 * PITCH * 2)    // 10240: one 128x32 sub-tile
#define STAGE_OP    (2 * HALF_BYTES)     // 20480: one operand, one BK=64 stage
#define NSTAGE 2

typedef unsigned int u32;

// ---------------------------------------------------------------------------
// Device scratch (no allocations allowed)
// ---------------------------------------------------------------------------
__device__ __nv_bfloat16 g_xn[(size_t)MTOT * DD];      // LN output (bf16)
__device__ __nv_bfloat16 g_wq[(size_t)DD * DD];        // Wq bf16
__device__ __nv_bfloat16 g_wk[(size_t)DD * DD];        // Wk bf16
__device__ __nv_bfloat16 g_q [(size_t)MTOT * DD];      // Q bf16
__device__ __nv_bfloat16 g_k [(size_t)MTOT * DD];      // K bf16
__device__ float         g_p [(size_t)BB * SS * SS];   // scores fp32
__device__ __nv_bfloat16 g_pb[(size_t)BB * SS * SS];   // probs bf16
__device__ __nv_bfloat16 g_xt[(size_t)BB * DD * SS];   // x^T bf16 [b][d][s]

// ---------------------------------------------------------------------------
__device__ __forceinline__ u32 smem_u32(const void* p) {
    u32 a;
    asm("{ .reg .u64 t; cvta.to.shared.u64 t, %1; cvt.u32.u64 %0, t; }" : "=r"(a) : "l"(p));
    return a;
}
#define CP_ASYNC16(sa, ga) \
    asm volatile("cp.async.cg.shared.global [%0], [%1], 16;" :: "r"(sa), "l"(ga) : "memory")
#define CP_COMMIT()  asm volatile("cp.async.commit_group;" ::: "memory")
#define CP_WAIT(n)   asm volatile("cp.async.wait_group %0;" :: "n"(n) : "memory")
#define LDSM_X4(r0, r1, r2, r3, addr) \
    asm volatile("ldmatrix.sync.aligned.m8n8.x4.shared.b16 {%0,%1,%2,%3}, [%4];" \
        : "=r"(r0), "=r"(r1), "=r"(r2), "=r"(r3) : "r"(addr))

__device__ __forceinline__ void mma16816(float* c, const u32* a, u32 b0, u32 b1) {
    asm volatile(
        "mma.sync.aligned.m16n8k16.row.col.f32.bf16.bf16.f32 "
        "{%0,%1,%2,%3}, {%4,%5,%6,%7}, {%8,%9}, {%0,%1,%2,%3};"
        : "+f"(c[0]), "+f"(c[1]), "+f"(c[2]), "+f"(c[3])
        : "r"(a[0]), "r"(a[1]), "r"(a[2]), "r"(a[3]), "r"(b0), "r"(b1));
}

// ---------------------------------------------------------------------------
// HMMA GEMM:  C[m,n] = sum_k A[m,k] * B[n,k]  (+bias)(+resid)
// A:[M,K] bf16 K-major, B:[N,K] bf16 K-major. Block 128x128, BK=64.
// 256 threads = 8 warps (4m x 2n), warp tile 32x64, m16n8k16 fragments.
// 2-stage cp.async double buffer, 64 MMAs/warp between barriers.
// Stage layout per operand: [2 halves][128 rows][PITCH bf16].
// ---------------------------------------------------------------------------
template <bool BIAS, bool RESID, bool OUTBF16>
__global__ __launch_bounds__(256, 2) void mma_gemm(
    const __nv_bfloat16* __restrict__ A, const __nv_bfloat16* __restrict__ B,
    void* __restrict__ Cv,
    const float* __restrict__ bias, const float* __restrict__ resid,
    int N, int K, long aStride, long bStride, long cStride)
{
    extern __shared__ char smem[];
    const u32 aTile0 = smem_u32(smem);
    const u32 bTile0 = aTile0 + NSTAGE * STAGE_OP;

    const int tid = threadIdx.x;
    const int wid = tid >> 5, lane = tid & 31;
    const int wm = wid & 3, wn = wid >> 2;          // 4 x 2 warp grid
    const int g = lane >> 2, t = lane & 3;          // mma fragment coords
    const int m0 = blockIdx.y * 128, n0 = blockIdx.x * 128;
    const int z = blockIdx.z;

    A += (size_t)z * aStride + (size_t)m0 * K;
    B += (size_t)z * bStride + (size_t)n0 * K;

    const int NC = K / BK;

    // cp.async mapping: per operand per stage = 2048 16B segments? No:
    // 128 rows x 64 bf16 = 16384 B = 1024 segs; 4 per thread.
    // seg pattern is constant per thread: seg = tid&7 within a row.
    const int seg  = tid & 7;
    const int half = (seg >> 2);             // k-half 0/1
    const int kin  = (seg & 3) * 8;          // bf16 offset within half
    const int gcol = half * 32 + kin;        // global k offset within stage
    const int rbase = tid >> 3;              // rows rbase + {0,32,64,96}
    const u32 sColOff = half * HALF_BYTES + kin * 2;

    // ldmatrix per-lane base (row = lane&15, kcol = (lane>>4)*8 bf16)
    const int lr = lane & 15, lk = (lane >> 4) * 8;
    const u32 aLds = aTile0 + (wm * 32 + lr) * (PITCH * 2) + lk * 2;
    const u32 bLds = bTile0 + (wn * 64 + lr) * (PITCH * 2) + lk * 2;

    float acc[2][8][4];
    #pragma unroll
    for (int mt = 0; mt < 2; mt++)
        #pragma unroll
        for (int nt = 0; nt < 8; nt++)
            #pragma unroll
            for (int i = 0; i < 4; i++) acc[mt][nt][i] = 0.f;

    // prologue: stage 0
    {
        #pragma unroll
        for (int i = 0; i < 4; i++) {
            const int r = rbase + i * 32;
            CP_ASYNC16(aTile0 + sColOff + r * (PITCH * 2), A + (size_t)r * K + gcol);
            CP_ASYNC16(bTile0 + sColOff + r * (PITCH * 2), B + (size_t)r * K + gcol);
        }
        CP_COMMIT();
    }

    for (int c = 0; c < NC; ++c) {
        const int buf = c & 1;
        CP_WAIT(0);
        __syncthreads();

        if (c + 1 < NC) {
            const int nb = buf ^ 1;
            const __nv_bfloat16* Ak = A + (size_t)(c + 1) * BK;
            const __nv_bfloat16* Bk = B + (size_t)(c + 1) * BK;
            const u32 so = nb * STAGE_OP + sColOff;
            #pragma unroll
            for (int i = 0; i < 4; i++) {
                const int r = rbase + i * 32;
                CP_ASYNC16(aTile0 + so + r * (PITCH * 2), Ak + (size_t)r * K + gcol);
                CP_ASYNC16(bTile0 + so + r * (PITCH * 2), Bk + (size_t)r * K + gcol);
            }
            CP_COMMIT();
        }

        const u32 so = buf * STAGE_OP;
        #pragma unroll
        for (int kk = 0; kk < 4; kk++) {
            const u32 ko = (kk >> 1) * HALF_BYTES + (kk & 1) * 32;
            u32 a[2][4], b[4][4];
            #pragma unroll
            for (int mt = 0; mt < 2; mt++)
                LDSM_X4(a[mt][0], a[mt][1], a[mt][2], a[mt][3],
                        aLds + so + ko + mt * (16 * PITCH * 2));
            #pragma unroll
            for (int np = 0; np < 4; np++)
                LDSM_X4(b[np][0], b[np][1], b[np][2], b[np][3],
                        bLds + so + ko + np * (16 * PITCH * 2));
            // b[np] = { b_{2np}[0], b_{2np+1}[0], b_{2np}[1], b_{2np+1}[1] }
            #pragma unroll
            for (int mt = 0; mt < 2; mt++)
                #pragma unroll
                for (int nt = 0; nt < 8; nt++)
                    mma16816(acc[mt][nt], a[mt], b[nt >> 1][nt & 1], b[nt >> 1][2 + (nt & 1)]);
        }
    }

    // Epilogue
    #pragma unroll
    for (int mt = 0; mt < 2; mt++) {
        #pragma unroll
        for (int nt = 0; nt < 8; nt++) {
            const int row = m0 + wm * 32 + mt * 16 + g;
            const int col = n0 + wn * 64 + nt * 8 + 2 * t;
            float v0 = acc[mt][nt][0], v1 = acc[mt][nt][1];
            float v2 = acc[mt][nt][2], v3 = acc[mt][nt][3];
            if (BIAS) {
                float b0 = bias[col], b1 = bias[col + 1];
                v0 += b0; v1 += b1; v2 += b0; v3 += b1;
            }
            if (OUTBF16) {
                __nv_bfloat16* Cb = (__nv_bfloat16*)Cv + (size_t)z * cStride;
                *(__nv_bfloat162*)(Cb + (size_t)row * N + col) = __floats2bfloat162_rn(v0, v1);
                *(__nv_bfloat162*)(Cb + (size_t)(row + 8) * N + col) = __floats2bfloat162_rn(v2, v3);
            } else {
                float* Cf = (float*)Cv + (size_t)z * cStride;
                if (RESID) {
                    const float* R = resid + (size_t)z * cStride;
                    float2 ra = *(const float2*)(R + (size_t)row * N + col);
                    float2 rb = *(const float2*)(R + (size_t)(row + 8) * N + col);
                    v0 += ra.x; v1 += ra.y; v2 += rb.x; v3 += rb.y;
                }
                *(float2*)(Cf + (size_t)row * N + col) = make_float2(v0, v1);
                *(float2*)(Cf + (size_t)(row + 8) * N + col) = make_float2(v2, v3);
            }
        }
    }
}

// ---------------------------------------------------------------------------
// Reductions + elementwise kernels
// ---------------------------------------------------------------------------
__device__ __forceinline__ float blockReduceSum(float v) {
    __shared__ float sh[32];
    int lane = threadIdx.x & 31, wid = threadIdx.x >> 5;
    #pragma unroll
    for (int o = 16; o; o >>= 1) v += __shfl_down_sync(0xffffffffu, v, o);
    if (lane == 0) sh[wid] = v;
    __syncthreads();
    float r = (threadIdx.x < (blockDim.x >> 5)) ? sh[threadIdx.x] : 0.f;
    if (wid == 0) {
        #pragma unroll
        for (int o = 16; o; o >>= 1) r += __shfl_down_sync(0xffffffffu, r, o);
        if (lane == 0) sh[0] = r;
    }
    __syncthreads();
    float out = sh[0];
    __syncthreads();
    return out;
}
__device__ __forceinline__ float blockReduceMax(float v) {
    __shared__ float sh[32];
    int lane = threadIdx.x & 31, wid = threadIdx.x >> 5;
    #pragma unroll
    for (int o = 16; o; o >>= 1) v = fmaxf(v, __shfl_down_sync(0xffffffffu, v, o));
    if (lane == 0) sh[wid] = v;
    __syncthreads();
    float r = (threadIdx.x < (blockDim.x >> 5)) ? sh[threadIdx.x] : -3.4e38f;
    if (wid == 0) {
        #pragma unroll
        for (int o = 16; o; o >>= 1) r = fmaxf(r, __shfl_down_sync(0xffffffffu, r, o));
        if (lane == 0) sh[0] = r;
    }
    __syncthreads();
    float out = sh[0];
    __syncthreads();
    return out;
}

__global__ __launch_bounds__(256) void ln_kernel(const float* __restrict__ x,
                                                 const float* __restrict__ g,
                                                 const float* __restrict__ b) {
    int row = blockIdx.x, t = threadIdx.x;
    const float* xr = x + (size_t)row * DD;
    float v[3];
    #pragma unroll
    for (int i = 0; i < 3; i++) v[i] = xr[t + i * 256];
    float mean = blockReduceSum(v[0] + v[1] + v[2]) * (1.0f / DD);
    float q = 0.f;
    #pragma unroll
    for (int i = 0; i < 3; i++) { float d = v[i] - mean; q += d * d; }
    float inv = rsqrtf(blockReduceSum(q) * (1.0f / DD) + 1e-5f);
    __nv_bfloat16* o = g_xn + (size_t)row * DD;
    #pragma unroll
    for (int i = 0; i < 3; i++) {
        int c = t + i * 256;
        o[c] = __float2bfloat16_rn((v[i] - mean) * inv * g[c] + b[c]);
    }
}

__global__ __launch_bounds__(256) void convw_kernel(const float* __restrict__ Wq,
                                                    const float* __restrict__ Wk) {
    int i = blockIdx.x * 256 + threadIdx.x;
    if (i < DD * DD) {
        g_wq[i] = __float2bfloat16_rn(Wq[i]);
        g_wk[i] = __float2bfloat16_rn(Wk[i]);
    }
}

__global__ __launch_bounds__(256) void transpose_kernel(const float* __restrict__ x) {
    __shared__ float t[32][33];
    int b = blockIdx.z;
    int s0 = blockIdx.x * 32, d0 = blockIdx.y * 32;
    int tx = threadIdx.x & 31, ty = threadIdx.x >> 5;
    #pragma unroll
    for (int i = 0; i < 4; i++)
        t[ty + i * 8][tx] = x[(size_t)b * SS * DD + (size_t)(s0 + ty + i * 8) * DD + d0 + tx];
    __syncthreads();
    #pragma unroll
    for (int i = 0; i < 4; i++)
        g_xt[(size_t)b * DD * SS + (size_t)(d0 + ty + i * 8) * SS + s0 + tx] =
            __float2bfloat16_rn(t[tx][ty + i * 8]);
}

__global__ __launch_bounds__(256) void softmax_kernel() {
    const float alpha = 0.036084391824351615f;   // 1/sqrt(768)
    const float4* row = (const float4*)(g_p + (size_t)blockIdx.x * SS);
    __nv_bfloat16* orow = g_pb + (size_t)blockIdx.x * SS;
    int t = threadIdx.x;
    float4 va = row[t];
    float4 vb = row[t + 256];
    float v[8] = {va.x, va.y, va.z, va.w, vb.x, vb.y, vb.z, vb.w};
    #pragma unroll
    for (int i = 0; i < 8; i++) v[i] *= alpha;
    float m = v[0];
    #pragma unroll
    for (int i = 1; i < 8; i++) m = fmaxf(m, v[i]);
    m = blockReduceMax(m);
    float s = 0.f;
    #pragma unroll
    for (int i = 0; i < 8; i++) { v[i] = __expf(v[i] - m); s += v[i]; }
    s = blockReduceSum(s);
    float inv = 1.0f / s;
    __nv_bfloat162 o01 = __floats2bfloat162_rn(v[0] * inv, v[1] * inv);
    __nv_bfloat162 o23 = __floats2bfloat162_rn(v[2] * inv, v[3] * inv);
    __nv_bfloat162 o45 = __floats2bfloat162_rn(v[4] * inv, v[5] * inv);
    __nv_bfloat162 o67 = __floats2bfloat162_rn(v[6] * inv, v[7] * inv);
    uint2 pa, pb;
    pa.x = *(u32*)&o01; pa.y = *(u32*)&o23;
    pb.x = *(u32*)&o45; pb.y = *(u32*)&o67;
    *(uint2*)(orow + t * 4) = pa;
    *(uint2*)(orow + (t + 256) * 4) = pb;
}

// ---------------------------------------------------------------------------
extern "C" void kernel_launch(void* const* d_in, const int* in_sizes, int n_in,
                              void* d_out, int out_size) {
    const float* x    = (const float*)d_in[0];
    const float* ln_g = (const float*)d_in[1];
    const float* ln_b = (const float*)d_in[2];
    const float* Wq   = (const float*)d_in[3];
    const float* bq   = (const float*)d_in[4];
    const float* Wk   = (const float*)d_in[5];
    const float* bk   = (const float*)d_in[6];
    float* out = (float*)d_out;

    const int SMEM_DYN = NSTAGE * STAGE_OP * 2;   // 81920
    cudaFuncSetAttribute(mma_gemm<true,  false, true >, cudaFuncAttributeMaxDynamicSharedMemorySize, SMEM_DYN);
    cudaFuncSetAttribute(mma_gemm<false, false, false>, cudaFuncAttributeMaxDynamicSharedMemorySize, SMEM_DYN);
    cudaFuncSetAttribute(mma_gemm<false, true,  false>, cudaFuncAttributeMaxDynamicSharedMemorySize, SMEM_DYN);

    __nv_bfloat16 *p_xn, *p_wq, *p_wk, *p_q, *p_k, *p_pb, *p_xt;
    float* p_p;
    cudaGetSymbolAddress((void**)&p_xn, g_xn);
    cudaGetSymbolAddress((void**)&p_wq, g_wq);
    cudaGetSymbolAddress((void**)&p_wk, g_wk);
    cudaGetSymbolAddress((void**)&p_q,  g_q);
    cudaGetSymbolAddress((void**)&p_k,  g_k);
    cudaGetSymbolAddress((void**)&p_p,  g_p);
    cudaGetSymbolAddress((void**)&p_pb, g_pb);
    cudaGetSymbolAddress((void**)&p_xt, g_xt);

    ln_kernel<<<MTOT, 256>>>(x, ln_g, ln_b);
    convw_kernel<<<(DD * DD + 255) / 256, 256>>>(Wq, Wk);
    transpose_kernel<<<dim3(SS / 32, DD / 32, BB), 256>>>(x);

    // Q = xn @ Wq^T + bq ; K = xn @ Wk^T + bk   (M=16384, N=768, K=768)
    mma_gemm<true, false, true><<<dim3(DD / 128, MTOT / 128, 1), 256, SMEM_DYN>>>(
        p_xn, p_wq, p_q, bq, nullptr, DD, DD, 0, 0, 0);
    mma_gemm<true, false, true><<<dim3(DD / 128, MTOT / 128, 1), 256, SMEM_DYN>>>(
        p_xn, p_wk, p_k, bk, nullptr, DD, DD, 0, 0, 0);

    // scores = Q @ K^T (unscaled; softmax applies 1/sqrt(D))
    mma_gemm<false, false, false><<<dim3(SS / 128, SS / 128, BB), 256, SMEM_DYN>>>(
        p_q, p_k, p_p, nullptr, nullptr, SS, DD,
        (long)SS * DD, (long)SS * DD, (long)SS * SS);

    softmax_kernel<<<BB * SS, 256>>>();

    // out = P @ x + x   (A = P bf16 [S,S], B = x^T bf16 [D,S])
    mma_gemm<false, true, false><<<dim3(DD / 128, SS / 128, BB), 256, SMEM_DYN>>>(
        p_pb, p_xt, out, nullptr, x, DD, SS,
        (long)SS * SS, (long)DD * SS, (long)SS * DD);
}

// round 7
// speedup vs baseline: 1.1215x; 1.1215x over previous
#include <cuda_runtime.h>
#include <cuda_bf16.h>

#define DD   768
#define BB   8
#define SS   2048
#define MTOT (BB * SS)
#define BK   32
#define PITCH 40                        // bf16 per smem row (80B, conflict-free)
#define STAGE_BYTES (128 * PITCH * 2)   // 10240 per operand tile
#define NSTAGE 4

typedef unsigned int u32;

// ---------------------------------------------------------------------------
// Device scratch (no allocations allowed)
// ---------------------------------------------------------------------------
__device__ __nv_bfloat16 g_xn [(size_t)MTOT * DD];      // LN output (bf16)
__device__ __nv_bfloat16 g_wqk[(size_t)2 * DD * DD];    // [Wq;Wk] stacked bf16
__device__ float         g_bqk[2 * DD];                 // [bq;bk] stacked fp32
__device__ __nv_bfloat16 g_q  [(size_t)MTOT * DD];      // Q bf16
__device__ __nv_bfloat16 g_k  [(size_t)MTOT * DD];      // K bf16
__device__ float         g_p  [(size_t)BB * SS * SS];   // scores fp32
__device__ __nv_bfloat16 g_pb [(size_t)BB * SS * SS];   // probs bf16
__device__ __nv_bfloat16 g_xt [(size_t)BB * DD * SS];   // x^T bf16 [b][d][s]

// ---------------------------------------------------------------------------
__device__ __forceinline__ u32 smem_u32(const void* p) {
    u32 a;
    asm("{ .reg .u64 t; cvta.to.shared.u64 t, %1; cvt.u32.u64 %0, t; }" : "=r"(a) : "l"(p));
    return a;
}
#define CP_ASYNC16(sa, ga) \
    asm volatile("cp.async.cg.shared.global [%0], [%1], 16;" :: "r"(sa), "l"(ga) : "memory")
#define CP_COMMIT()  asm volatile("cp.async.commit_group;" ::: "memory")
#define CP_WAIT(n)   asm volatile("cp.async.wait_group %0;" :: "n"(n) : "memory")
#define LDSM_X4(r0, r1, r2, r3, addr) \
    asm volatile("ldmatrix.sync.aligned.m8n8.x4.shared.b16 {%0,%1,%2,%3}, [%4];" \
        : "=r"(r0), "=r"(r1), "=r"(r2), "=r"(r3) : "r"(addr))

__device__ __forceinline__ void mma16816(float* c, const u32* a, u32 b0, u32 b1) {
    asm volatile(
        "mma.sync.aligned.m16n8k16.row.col.f32.bf16.bf16.f32 "
        "{%0,%1,%2,%3}, {%4,%5,%6,%7}, {%8,%9}, {%0,%1,%2,%3};"
        : "+f"(c[0]), "+f"(c[1]), "+f"(c[2]), "+f"(c[3])
        : "r"(a[0]), "r"(a[1]), "r"(a[2]), "r"(a[3]), "r"(b0), "r"(b1));
}

// ---------------------------------------------------------------------------
// HMMA GEMM:  C[m,n] = sum_k A[m,k] * B[n,k]  (+bias)(+resid)
// A:[M,K] bf16 K-major, B:[N,K] bf16 K-major. Block 128x128, BK=32.
// 256 threads = 8 warps (4m x 2n), warp tile 32x64, m16n8k16 fragments.
// 4-stage cp.async pipeline (wait_group 2), ldmatrix.x4, 1 sync / iter.
// SPLIT: B is stacked [N0-block | N1-block]; outputs route to Cv / Cv2
//        (bf16, row stride N), bias indexed in stacked column space.
// ---------------------------------------------------------------------------
template <bool BIAS, bool RESID, bool OUTBF16, bool SPLIT>
__global__ __launch_bounds__(256, 2) void mma_gemm(
    const __nv_bfloat16* __restrict__ A, const __nv_bfloat16* __restrict__ B,
    void* __restrict__ Cv, void* __restrict__ Cv2,
    const float* __restrict__ bias, const float* __restrict__ resid,
    int N, int K, long aStride, long bStride, long cStride)
{
    extern __shared__ char smem[];
    const u32 aTile0 = smem_u32(smem);
    const u32 bTile0 = aTile0 + NSTAGE * STAGE_BYTES;

    const int tid = threadIdx.x;
    const int wid = tid >> 5, lane = tid & 31;
    const int wm = wid & 3, wn = wid >> 2;          // 4 x 2 warp grid
    const int g = lane >> 2, t = lane & 3;          // mma fragment coords
    const int m0 = blockIdx.y * 128, n0 = blockIdx.x * 128;
    const int z = blockIdx.z;

    A += (size_t)z * aStride + (size_t)m0 * K;
    B += (size_t)z * bStride + (size_t)n0 * K;

    const int NC = K / BK;
    // cp.async mapping: 512 16B segments per operand tile, 2 per thread
    const int r0 = tid >> 2, c0 = (tid & 3) * 8;
    const int r1 = r0 + 64;
    const u32 sA0 = aTile0 + r0 * (PITCH * 2) + c0 * 2;
    const u32 sA1 = aTile0 + r1 * (PITCH * 2) + c0 * 2;
    const u32 sB0 = bTile0 + r0 * (PITCH * 2) + c0 * 2;
    const u32 sB1 = bTile0 + r1 * (PITCH * 2) + c0 * 2;

    // ldmatrix per-lane base addresses (row = lane&15, kcol = (lane>>4)*8)
    const int lr = lane & 15, lk = (lane >> 4) * 8;
    const u32 aLds = aTile0 + (wm * 32 + lr) * (PITCH * 2) + lk * 2;
    const u32 bLds = bTile0 + (wn * 64 + lr) * (PITCH * 2) + lk * 2;

    float acc[2][8][4];
    #pragma unroll
    for (int mt = 0; mt < 2; mt++)
        #pragma unroll
        for (int nt = 0; nt < 8; nt++)
            #pragma unroll
            for (int i = 0; i < 4; i++) acc[mt][nt][i] = 0.f;

    // prologue: stages 0..2
    #pragma unroll
    for (int s = 0; s < NSTAGE - 1; s++) {
        const __nv_bfloat16* Ak = A + (size_t)s * BK;
        const __nv_bfloat16* Bk = B + (size_t)s * BK;
        const u32 so = s * STAGE_BYTES;
        CP_ASYNC16(sA0 + so, Ak + (size_t)r0 * K + c0);
        CP_ASYNC16(sA1 + so, Ak + (size_t)r1 * K + c0);
        CP_ASYNC16(sB0 + so, Bk + (size_t)r0 * K + c0);
        CP_ASYNC16(sB1 + so, Bk + (size_t)r1 * K + c0);
        CP_COMMIT();
    }

    int st = 0;
    for (int c = 0; c < NC; ++c) {
        CP_WAIT(2);                     // stage c's group complete
        __syncthreads();

        // prefetch stage c+3 into the slot vacated at c-1
        if (c + NSTAGE - 1 < NC) {
            int ps = st + NSTAGE - 1; if (ps >= NSTAGE) ps -= NSTAGE;
            const __nv_bfloat16* Ak = A + (size_t)(c + NSTAGE - 1) * BK;
            const __nv_bfloat16* Bk = B + (size_t)(c + NSTAGE - 1) * BK;
            const u32 so = ps * STAGE_BYTES;
            CP_ASYNC16(sA0 + so, Ak + (size_t)r0 * K + c0);
            CP_ASYNC16(sA1 + so, Ak + (size_t)r1 * K + c0);
            CP_ASYNC16(sB0 + so, Bk + (size_t)r0 * K + c0);
            CP_ASYNC16(sB1 + so, Bk + (size_t)r1 * K + c0);
        }
        CP_COMMIT();

        const u32 so = st * STAGE_BYTES;
        #pragma unroll
        for (int kk = 0; kk < 2; kk++) {
            u32 a[2][4], b[4][4];
            #pragma unroll
            for (int mt = 0; mt < 2; mt++)
                LDSM_X4(a[mt][0], a[mt][1], a[mt][2], a[mt][3],
                        aLds + so + mt * (16 * PITCH * 2) + kk * 32);
            #pragma unroll
            for (int np = 0; np < 4; np++)
                LDSM_X4(b[np][0], b[np][1], b[np][2], b[np][3],
                        bLds + so + np * (16 * PITCH * 2) + kk * 32);
            // b[np] = { b_{2np}[0], b_{2np+1}[0], b_{2np}[1], b_{2np+1}[1] }
            #pragma unroll
            for (int mt = 0; mt < 2; mt++)
                #pragma unroll
                for (int nt = 0; nt < 8; nt++)
                    mma16816(acc[mt][nt], a[mt], b[nt >> 1][nt & 1], b[nt >> 1][2 + (nt & 1)]);
        }
        st = st + 1; if (st >= NSTAGE) st = 0;
    }

    // Epilogue
    __nv_bfloat16* CbBase = 0;
    int colShift = 0;
    if (SPLIT) {
        CbBase = (__nv_bfloat16*)((n0 < DD) ? Cv : Cv2);
        colShift = (n0 < DD) ? 0 : DD;
    }
    #pragma unroll
    for (int mt = 0; mt < 2; mt++) {
        #pragma unroll
        for (int nt = 0; nt < 8; nt++) {
            const int row = m0 + wm * 32 + mt * 16 + g;
            const int col = n0 + wn * 64 + nt * 8 + 2 * t;
            float v0 = acc[mt][nt][0], v1 = acc[mt][nt][1];
            float v2 = acc[mt][nt][2], v3 = acc[mt][nt][3];
            if (BIAS) {
                float b0 = bias[col], b1 = bias[col + 1];
                v0 += b0; v1 += b1; v2 += b0; v3 += b1;
            }
            if (OUTBF16) {
                __nv_bfloat16* Cb;
                int cc;
                if (SPLIT) { Cb = CbBase; cc = col - colShift; }
                else       { Cb = (__nv_bfloat16*)Cv + (size_t)z * cStride; cc = col; }
                *(__nv_bfloat162*)(Cb + (size_t)row * N + cc) = __floats2bfloat162_rn(v0, v1);
                *(__nv_bfloat162*)(Cb + (size_t)(row + 8) * N + cc) = __floats2bfloat162_rn(v2, v3);
            } else {
                float* Cf = (float*)Cv + (size_t)z * cStride;
                if (RESID) {
                    const float* R = resid + (size_t)z * cStride;
                    float2 ra = *(const float2*)(R + (size_t)row * N + col);
                    float2 rb = *(const float2*)(R + (size_t)(row + 8) * N + col);
                    v0 += ra.x; v1 += ra.y; v2 += rb.x; v3 += rb.y;
                }
                *(float2*)(Cf + (size_t)row * N + col) = make_float2(v0, v1);
                *(float2*)(Cf + (size_t)(row + 8) * N + col) = make_float2(v2, v3);
            }
        }
    }
}

// ---------------------------------------------------------------------------
// Reductions + elementwise kernels
// ---------------------------------------------------------------------------
__device__ __forceinline__ float blockReduceSum(float v) {
    __shared__ float sh[32];
    int lane = threadIdx.x & 31, wid = threadIdx.x >> 5;
    #pragma unroll
    for (int o = 16; o; o >>= 1) v += __shfl_down_sync(0xffffffffu, v, o);
    if (lane == 0) sh[wid] = v;
    __syncthreads();
    float r = (threadIdx.x < (blockDim.x >> 5)) ? sh[threadIdx.x] : 0.f;
    if (wid == 0) {
        #pragma unroll
        for (int o = 16; o; o >>= 1) r += __shfl_down_sync(0xffffffffu, r, o);
        if (lane == 0) sh[0] = r;
    }
    __syncthreads();
    float out = sh[0];
    __syncthreads();
    return out;
}
__device__ __forceinline__ float blockReduceMax(float v) {
    __shared__ float sh[32];
    int lane = threadIdx.x & 31, wid = threadIdx.x >> 5;
    #pragma unroll
    for (int o = 16; o; o >>= 1) v = fmaxf(v, __shfl_down_sync(0xffffffffu, v, o));
    if (lane == 0) sh[wid] = v;
    __syncthreads();
    float r = (threadIdx.x < (blockDim.x >> 5)) ? sh[threadIdx.x] : -3.4e38f;
    if (wid == 0) {
        #pragma unroll
        for (int o = 16; o; o >>= 1) r = fmaxf(r, __shfl_down_sync(0xffffffffu, r, o));
        if (lane == 0) sh[0] = r;
    }
    __syncthreads();
    float out = sh[0];
    __syncthreads();
    return out;
}

__global__ __launch_bounds__(256) void ln_kernel(const float* __restrict__ x,
                                                 const float* __restrict__ g,
                                                 const float* __restrict__ b) {
    int row = blockIdx.x, t = threadIdx.x;
    const float* xr = x + (size_t)row * DD;
    float v[3];
    #pragma unroll
    for (int i = 0; i < 3; i++) v[i] = xr[t + i * 256];
    float mean = blockReduceSum(v[0] + v[1] + v[2]) * (1.0f / DD);
    float q = 0.f;
    #pragma unroll
    for (int i = 0; i < 3; i++) { float d = v[i] - mean; q += d * d; }
    float inv = rsqrtf(blockReduceSum(q) * (1.0f / DD) + 1e-5f);
    __nv_bfloat16* o = g_xn + (size_t)row * DD;
    #pragma unroll
    for (int i = 0; i < 3; i++) {
        int c = t + i * 256;
        o[c] = __float2bfloat16_rn((v[i] - mean) * inv * g[c] + b[c]);
    }
}

// Stack [Wq;Wk] -> g_wqk (bf16) and [bq;bk] -> g_bqk (fp32)
__global__ __launch_bounds__(256) void convw_kernel(const float* __restrict__ Wq,
                                                    const float* __restrict__ Wk,
                                                    const float* __restrict__ bq,
                                                    const float* __restrict__ bk) {
    int i = blockIdx.x * 256 + threadIdx.x;
    if (i < DD * DD) {
        g_wqk[i] = __float2bfloat16_rn(Wq[i]);
        g_wqk[(size_t)DD * DD + i] = __float2bfloat16_rn(Wk[i]);
    }
    if (i < DD) {
        g_bqk[i] = bq[i];
        g_bqk[DD + i] = bk[i];
    }
}

__global__ __launch_bounds__(256) void transpose_kernel(const float* __restrict__ x) {
    __shared__ float t[32][33];
    int b = blockIdx.z;
    int s0 = blockIdx.x * 32, d0 = blockIdx.y * 32;
    int tx = threadIdx.x & 31, ty = threadIdx.x >> 5;
    #pragma unroll
    for (int i = 0; i < 4; i++)
        t[ty + i * 8][tx] = x[(size_t)b * SS * DD + (size_t)(s0 + ty + i * 8) * DD + d0 + tx];
    __syncthreads();
    #pragma unroll
    for (int i = 0; i < 4; i++)
        g_xt[(size_t)b * DD * SS + (size_t)(d0 + ty + i * 8) * SS + s0 + tx] =
            __float2bfloat16_rn(t[tx][ty + i * 8]);
}

__global__ __launch_bounds__(256) void softmax_kernel() {
    const float alpha = 0.036084391824351615f;   // 1/sqrt(768)
    const float4* row = (const float4*)(g_p + (size_t)blockIdx.x * SS);
    __nv_bfloat16* orow = g_pb + (size_t)blockIdx.x * SS;
    int t = threadIdx.x;
    float4 va = row[t];
    float4 vb = row[t + 256];
    float v[8] = {va.x, va.y, va.z, va.w, vb.x, vb.y, vb.z, vb.w};
    #pragma unroll
    for (int i = 0; i < 8; i++) v[i] *= alpha;
    float m = v[0];
    #pragma unroll
    for (int i = 1; i < 8; i++) m = fmaxf(m, v[i]);
    m = blockReduceMax(m);
    float s = 0.f;
    #pragma unroll
    for (int i = 0; i < 8; i++) { v[i] = __expf(v[i] - m); s += v[i]; }
    s = blockReduceSum(s);
    float inv = 1.0f / s;
    __nv_bfloat162 o01 = __floats2bfloat162_rn(v[0] * inv, v[1] * inv);
    __nv_bfloat162 o23 = __floats2bfloat162_rn(v[2] * inv, v[3] * inv);
    __nv_bfloat162 o45 = __floats2bfloat162_rn(v[4] * inv, v[5] * inv);
    __nv_bfloat162 o67 = __floats2bfloat162_rn(v[6] * inv, v[7] * inv);
    uint2 pa, pb;
    pa.x = *(u32*)&o01; pa.y = *(u32*)&o23;
    pb.x = *(u32*)&o45; pb.y = *(u32*)&o67;
    *(uint2*)(orow + t * 4) = pa;
    *(uint2*)(orow + (t + 256) * 4) = pb;
}

// ---------------------------------------------------------------------------
extern "C" void kernel_launch(void* const* d_in, const int* in_sizes, int n_in,
                              void* d_out, int out_size) {
    const float* x    = (const float*)d_in[0];
    const float* ln_g = (const float*)d_in[1];
    const float* ln_b = (const float*)d_in[2];
    const float* Wq   = (const float*)d_in[3];
    const float* bq   = (const float*)d_in[4];
    const float* Wk   = (const float*)d_in[5];
    const float* bk   = (const float*)d_in[6];
    float* out = (float*)d_out;

    const int SMEM_DYN = NSTAGE * STAGE_BYTES * 2;   // 81920
    cudaFuncSetAttribute(mma_gemm<true,  false, true,  true >, cudaFuncAttributeMaxDynamicSharedMemorySize, SMEM_DYN);
    cudaFuncSetAttribute(mma_gemm<false, false, false, false>, cudaFuncAttributeMaxDynamicSharedMemorySize, SMEM_DYN);
    cudaFuncSetAttribute(mma_gemm<false, true,  false, false>, cudaFuncAttributeMaxDynamicSharedMemorySize, SMEM_DYN);

    __nv_bfloat16 *p_xn, *p_wqk, *p_q, *p_k, *p_pb, *p_xt;
    float *p_p, *p_bqk;
    cudaGetSymbolAddress((void**)&p_xn,  g_xn);
    cudaGetSymbolAddress((void**)&p_wqk, g_wqk);
    cudaGetSymbolAddress((void**)&p_bqk, g_bqk);
    cudaGetSymbolAddress((void**)&p_q,   g_q);
    cudaGetSymbolAddress((void**)&p_k,   g_k);
    cudaGetSymbolAddress((void**)&p_p,   g_p);
    cudaGetSymbolAddress((void**)&p_pb,  g_pb);
    cudaGetSymbolAddress((void**)&p_xt,  g_xt);

    ln_kernel<<<MTOT, 256>>>(x, ln_g, ln_b);
    convw_kernel<<<(DD * DD + 255) / 256, 256>>>(Wq, Wk, bq, bk);
    transpose_kernel<<<dim3(SS / 32, DD / 32, BB), 256>>>(x);

    // [Q|K] = xn @ [Wq;Wk]^T + [bq;bk]   (M=16384, N=1536 stacked, K=768)
    mma_gemm<true, false, true, true><<<dim3(2 * DD / 128, MTOT / 128, 1), 256, SMEM_DYN>>>(
        p_xn, p_wqk, p_q, p_k, p_bqk, nullptr, DD, DD, 0, 0, 0);

    // scores = Q @ K^T (unscaled; softmax applies 1/sqrt(D))
    mma_gemm<false, false, false, false><<<dim3(SS / 128, SS / 128, BB), 256, SMEM_DYN>>>(
        p_q, p_k, p_p, nullptr, nullptr, nullptr, SS, DD,
        (long)SS * DD, (long)SS * DD, (long)SS * SS);

    softmax_kernel<<<BB * SS, 256>>>();

    // out = P @ x + x   (A = P bf16 [S,S], B = x^T bf16 [D,S])
    mma_gemm<false, true, false, false><<<dim3(DD / 128, SS / 128, BB), 256, SMEM_DYN>>>(
        p_pb, p_xt, out, nullptr, nullptr, x, DD, SS,
        (long)SS * SS, (long)DD * SS, (long)SS * DD);
}

// round 8
// speedup vs baseline: 1.2307x; 1.0974x over previous
#include <cuda_runtime.h>
#include <cuda_bf16.h>

#define DD   768
#define BB   8
#define SS   2048
#define MTOT (BB * SS)
#define BK   32
#define PITCH 40                        // bf16 per smem row (80B, conflict-free)
#define STAGE_BYTES (128 * PITCH * 2)   // 10240 per operand tile
#define NSTAGE 3

typedef unsigned int u32;

// ---------------------------------------------------------------------------
// Device scratch (no allocations allowed)
// ---------------------------------------------------------------------------
__device__ __nv_bfloat16 g_xn [(size_t)MTOT * DD];      // LN output (bf16)
__device__ __nv_bfloat16 g_wqT[(size_t)DD * DD];        // Wq^T bf16 [i][m]
__device__ __nv_bfloat16 g_wkT[(size_t)DD * DD];        // Wk^T bf16 [j][m]
__device__ __nv_bfloat16 g_mt [(size_t)DD * DD];        // M^T bf16, MT[j][i]=M[i][j]
__device__ __nv_bfloat16 g_g  [(size_t)MTOT * DD];      // G = xn @ M  bf16
__device__ float         g_p  [(size_t)BB * SS * SS];   // scores fp32
__device__ __nv_bfloat16 g_pb [(size_t)BB * SS * SS];   // probs bf16
__device__ __nv_bfloat16 g_xt [(size_t)BB * DD * SS];   // x^T bf16 [b][d][s]
__device__ float         g_w  [DD];                     // w = Wk^T bq
__device__ float         g_c  [MTOT];                   // c_row = xn_row . w

// ---------------------------------------------------------------------------
__device__ __forceinline__ u32 smem_u32(const void* p) {
    u32 a;
    asm("{ .reg .u64 t; cvta.to.shared.u64 t, %1; cvt.u32.u64 %0, t; }" : "=r"(a) : "l"(p));
    return a;
}
#define CP_ASYNC16(sa, ga) \
    asm volatile("cp.async.cg.shared.global [%0], [%1], 16;" :: "r"(sa), "l"(ga) : "memory")
#define CP_COMMIT()  asm volatile("cp.async.commit_group;" ::: "memory")
#define CP_WAIT(n)   asm volatile("cp.async.wait_group %0;" :: "n"(n) : "memory")
#define LDSM_X4(r0, r1, r2, r3, addr) \
    asm volatile("ldmatrix.sync.aligned.m8n8.x4.shared.b16 {%0,%1,%2,%3}, [%4];" \
        : "=r"(r0), "=r"(r1), "=r"(r2), "=r"(r3) : "r"(addr))

__device__ __forceinline__ void mma16816(float* c, const u32* a, u32 b0, u32 b1) {
    asm volatile(
        "mma.sync.aligned.m16n8k16.row.col.f32.bf16.bf16.f32 "
        "{%0,%1,%2,%3}, {%4,%5,%6,%7}, {%8,%9}, {%0,%1,%2,%3};"
        : "+f"(c[0]), "+f"(c[1]), "+f"(c[2]), "+f"(c[3])
        : "r"(a[0]), "r"(a[1]), "r"(a[2]), "r"(a[3]), "r"(b0), "r"(b1));
}

// ---------------------------------------------------------------------------
// HMMA GEMM (R5-proven mainloop): C[m,n] = sum_k A[m,k]*B[n,k] (+resid)
// 128x128 tile, BK=32, 3-stage cp.async, ldmatrix.x4, 1 sync/iter.
// ---------------------------------------------------------------------------
template <bool RESID, bool OUTBF16>
__global__ __launch_bounds__(256) void mma_gemm(
    const __nv_bfloat16* __restrict__ A, const __nv_bfloat16* __restrict__ B,
    void* __restrict__ Cv,
    const float* __restrict__ resid,
    int N, int K, long aStride, long bStride, long cStride)
{
    extern __shared__ char smem[];
    const u32 aTile0 = smem_u32(smem);
    const u32 bTile0 = aTile0 + NSTAGE * STAGE_BYTES;

    const int tid = threadIdx.x;
    const int wid = tid >> 5, lane = tid & 31;
    const int wm = wid & 3, wn = wid >> 2;          // 4 x 2 warp grid
    const int g = lane >> 2, t = lane & 3;          // mma fragment coords
    const int m0 = blockIdx.y * 128, n0 = blockIdx.x * 128;
    const int z = blockIdx.z;

    A += (size_t)z * aStride + (size_t)m0 * K;
    B += (size_t)z * bStride + (size_t)n0 * K;

    const int NC = K / BK;
    const int r0 = tid >> 2, c0 = (tid & 3) * 8;
    const int r1 = r0 + 64;
    const u32 sA0 = aTile0 + r0 * (PITCH * 2) + c0 * 2;
    const u32 sA1 = aTile0 + r1 * (PITCH * 2) + c0 * 2;
    const u32 sB0 = bTile0 + r0 * (PITCH * 2) + c0 * 2;
    const u32 sB1 = bTile0 + r1 * (PITCH * 2) + c0 * 2;

    const int lr = lane & 15, lk = (lane >> 4) * 8;
    const u32 aLds = aTile0 + (wm * 32 + lr) * (PITCH * 2) + lk * 2;
    const u32 bLds = bTile0 + (wn * 64 + lr) * (PITCH * 2) + lk * 2;

    float acc[2][8][4];
    #pragma unroll
    for (int mt = 0; mt < 2; mt++)
        #pragma unroll
        for (int nt = 0; nt < 8; nt++)
            #pragma unroll
            for (int i = 0; i < 4; i++) acc[mt][nt][i] = 0.f;

    #pragma unroll
    for (int s = 0; s < 2; s++) {
        const __nv_bfloat16* Ak = A + (size_t)s * BK;
        const __nv_bfloat16* Bk = B + (size_t)s * BK;
        const u32 so = s * STAGE_BYTES;
        CP_ASYNC16(sA0 + so, Ak + (size_t)r0 * K + c0);
        CP_ASYNC16(sA1 + so, Ak + (size_t)r1 * K + c0);
        CP_ASYNC16(sB0 + so, Bk + (size_t)r0 * K + c0);
        CP_ASYNC16(sB1 + so, Bk + (size_t)r1 * K + c0);
        CP_COMMIT();
    }

    int st = 0;
    for (int c = 0; c < NC; ++c) {
        CP_WAIT(1);
        __syncthreads();

        if (c + 2 < NC) {
            const int ps = (st + 2 >= NSTAGE) ? st + 2 - NSTAGE : st + 2;
            const __nv_bfloat16* Ak = A + (size_t)(c + 2) * BK;
            const __nv_bfloat16* Bk = B + (size_t)(c + 2) * BK;
            const u32 so = ps * STAGE_BYTES;
            CP_ASYNC16(sA0 + so, Ak + (size_t)r0 * K + c0);
            CP_ASYNC16(sA1 + so, Ak + (size_t)r1 * K + c0);
            CP_ASYNC16(sB0 + so, Bk + (size_t)r0 * K + c0);
            CP_ASYNC16(sB1 + so, Bk + (size_t)r1 * K + c0);
        }
        CP_COMMIT();

        const u32 so = st * STAGE_BYTES;
        #pragma unroll
        for (int kk = 0; kk < 2; kk++) {
            u32 a[2][4], b[4][4];
            #pragma unroll
            for (int mt = 0; mt < 2; mt++)
                LDSM_X4(a[mt][0], a[mt][1], a[mt][2], a[mt][3],
                        aLds + so + mt * (16 * PITCH * 2) + kk * 32);
            #pragma unroll
            for (int np = 0; np < 4; np++)
                LDSM_X4(b[np][0], b[np][1], b[np][2], b[np][3],
                        bLds + so + np * (16 * PITCH * 2) + kk * 32);
            #pragma unroll
            for (int mt = 0; mt < 2; mt++)
                #pragma unroll
                for (int nt = 0; nt < 8; nt++)
                    mma16816(acc[mt][nt], a[mt], b[nt >> 1][nt & 1], b[nt >> 1][2 + (nt & 1)]);
        }
        st = (st + 1 >= NSTAGE) ? 0 : st + 1;
    }

    // Epilogue
    #pragma unroll
    for (int mt = 0; mt < 2; mt++) {
        #pragma unroll
        for (int nt = 0; nt < 8; nt++) {
            const int row = m0 + wm * 32 + mt * 16 + g;
            const int col = n0 + wn * 64 + nt * 8 + 2 * t;
            float v0 = acc[mt][nt][0], v1 = acc[mt][nt][1];
            float v2 = acc[mt][nt][2], v3 = acc[mt][nt][3];
            if (OUTBF16) {
                __nv_bfloat16* Cb = (__nv_bfloat16*)Cv + (size_t)z * cStride;
                *(__nv_bfloat162*)(Cb + (size_t)row * N + col) = __floats2bfloat162_rn(v0, v1);
                *(__nv_bfloat162*)(Cb + (size_t)(row + 8) * N + col) = __floats2bfloat162_rn(v2, v3);
            } else {
                float* Cf = (float*)Cv + (size_t)z * cStride;
                if (RESID) {
                    const float* R = resid + (size_t)z * cStride;
                    float2 ra = *(const float2*)(R + (size_t)row * N + col);
                    float2 rb = *(const float2*)(R + (size_t)(row + 8) * N + col);
                    v0 += ra.x; v1 += ra.y; v2 += rb.x; v3 += rb.y;
                }
                *(float2*)(Cf + (size_t)row * N + col) = make_float2(v0, v1);
                *(float2*)(Cf + (size_t)(row + 8) * N + col) = make_float2(v2, v3);
            }
        }
    }
}

// ---------------------------------------------------------------------------
// Reductions
// ---------------------------------------------------------------------------
__device__ __forceinline__ float blockReduceSum(float v) {
    __shared__ float sh[32];
    int lane = threadIdx.x & 31, wid = threadIdx.x >> 5;
    #pragma unroll
    for (int o = 16; o; o >>= 1) v += __shfl_down_sync(0xffffffffu, v, o);
    if (lane == 0) sh[wid] = v;
    __syncthreads();
    float r = (threadIdx.x < (blockDim.x >> 5)) ? sh[threadIdx.x] : 0.f;
    if (wid == 0) {
        #pragma unroll
        for (int o = 16; o; o >>= 1) r += __shfl_down_sync(0xffffffffu, r, o);
        if (lane == 0) sh[0] = r;
    }
    __syncthreads();
    float out = sh[0];
    __syncthreads();
    return out;
}
__device__ __forceinline__ float blockReduceMax(float v) {
    __shared__ float sh[32];
    int lane = threadIdx.x & 31, wid = threadIdx.x >> 5;
    #pragma unroll
    for (int o = 16; o; o >>= 1) v = fmaxf(v, __shfl_down_sync(0xffffffffu, v, o));
    if (lane == 0) sh[wid] = v;
    __syncthreads();
    float r = (threadIdx.x < (blockDim.x >> 5)) ? sh[threadIdx.x] : -3.4e38f;
    if (wid == 0) {
        #pragma unroll
        for (int o = 16; o; o >>= 1) r = fmaxf(r, __shfl_down_sync(0xffffffffu, r, o));
        if (lane == 0) sh[0] = r;
    }
    __syncthreads();
    float out = sh[0];
    __syncthreads();
    return out;
}

// w[d] = sum_j bq[j] * Wk[j,d]   (one block per d)
__global__ __launch_bounds__(256) void w_kernel(const float* __restrict__ Wk,
                                                const float* __restrict__ bq) {
    int d = blockIdx.x, t = threadIdx.x;
    float s = 0.f;
    for (int j = t; j < DD; j += 256) s += bq[j] * Wk[(size_t)j * DD + d];
    s = blockReduceSum(s);
    if (t == 0) g_w[d] = s;
}

// LayerNorm -> bf16, plus c_row = xn_row . w
__global__ __launch_bounds__(256) void ln_kernel(const float* __restrict__ x,
                                                 const float* __restrict__ g,
                                                 const float* __restrict__ b) {
    int row = blockIdx.x, t = threadIdx.x;
    const float* xr = x + (size_t)row * DD;
    float v[3];
    #pragma unroll
    for (int i = 0; i < 3; i++) v[i] = xr[t + i * 256];
    float mean = blockReduceSum(v[0] + v[1] + v[2]) * (1.0f / DD);
    float q = 0.f;
    #pragma unroll
    for (int i = 0; i < 3; i++) { float d = v[i] - mean; q += d * d; }
    float inv = rsqrtf(blockReduceSum(q) * (1.0f / DD) + 1e-5f);
    __nv_bfloat16* o = g_xn + (size_t)row * DD;
    float cdot = 0.f;
    #pragma unroll
    for (int i = 0; i < 3; i++) {
        int c = t + i * 256;
        float xv = (v[i] - mean) * inv * g[c] + b[c];
        o[c] = __float2bfloat16_rn(xv);
        cdot += xv * g_w[c];
    }
    cdot = blockReduceSum(cdot);
    if (t == 0) g_c[row] = cdot;
}

// Transpose W fp32 [m][i] -> bf16 [i][m] for both weights
__global__ __launch_bounds__(256) void convwT_kernel(const float* __restrict__ Wq,
                                                     const float* __restrict__ Wk) {
    __shared__ float tq[32][33];
    __shared__ float tk[32][33];
    int m0 = blockIdx.x * 32, i0 = blockIdx.y * 32;
    int tx = threadIdx.x & 31, ty = threadIdx.x >> 5;
    #pragma unroll
    for (int r = 0; r < 4; r++) {
        tq[ty + r * 8][tx] = Wq[(size_t)(m0 + ty + r * 8) * DD + i0 + tx];
        tk[ty + r * 8][tx] = Wk[(size_t)(m0 + ty + r * 8) * DD + i0 + tx];
    }
    __syncthreads();
    #pragma unroll
    for (int r = 0; r < 4; r++) {
        g_wqT[(size_t)(i0 + ty + r * 8) * DD + m0 + tx] = __float2bfloat16_rn(tq[tx][ty + r * 8]);
        g_wkT[(size_t)(i0 + ty + r * 8) * DD + m0 + tx] = __float2bfloat16_rn(tk[tx][ty + r * 8]);
    }
}

// x [b][s][d] fp32 -> g_xt [b][d][s] bf16
__global__ __launch_bounds__(256) void transpose_kernel(const float* __restrict__ x) {
    __shared__ float t[32][33];
    int b = blockIdx.z;
    int s0 = blockIdx.x * 32, d0 = blockIdx.y * 32;
    int tx = threadIdx.x & 31, ty = threadIdx.x >> 5;
    #pragma unroll
    for (int i = 0; i < 4; i++)
        t[ty + i * 8][tx] = x[(size_t)b * SS * DD + (size_t)(s0 + ty + i * 8) * DD + d0 + tx];
    __syncthreads();
    #pragma unroll
    for (int i = 0; i < 4; i++)
        g_xt[(size_t)b * DD * SS + (size_t)(d0 + ty + i * 8) * SS + s0 + tx] =
            __float2bfloat16_rn(t[tx][ty + i * 8]);
}

// softmax over last dim with column bias c_t: probs = softmax(alpha*(s + c_t))
__global__ __launch_bounds__(256) void softmax_kernel() {
    const float alpha = 0.036084391824351615f;   // 1/sqrt(768)
    const int b = blockIdx.x / SS;
    const float4* row = (const float4*)(g_p + (size_t)blockIdx.x * SS);
    const float4* crow = (const float4*)(g_c + (size_t)b * SS);
    __nv_bfloat16* orow = g_pb + (size_t)blockIdx.x * SS;
    int t = threadIdx.x;
    float4 va = row[t];
    float4 vb = row[t + 256];
    float4 ca = crow[t];
    float4 cb = crow[t + 256];
    float v[8] = {va.x + ca.x, va.y + ca.y, va.z + ca.z, va.w + ca.w,
                  vb.x + cb.x, vb.y + cb.y, vb.z + cb.z, vb.w + cb.w};
    #pragma unroll
    for (int i = 0; i < 8; i++) v[i] *= alpha;
    float m = v[0];
    #pragma unroll
    for (int i = 1; i < 8; i++) m = fmaxf(m, v[i]);
    m = blockReduceMax(m);
    float s = 0.f;
    #pragma unroll
    for (int i = 0; i < 8; i++) { v[i] = __expf(v[i] - m); s += v[i]; }
    s = blockReduceSum(s);
    float inv = 1.0f / s;
    __nv_bfloat162 o01 = __floats2bfloat162_rn(v[0] * inv, v[1] * inv);
    __nv_bfloat162 o23 = __floats2bfloat162_rn(v[2] * inv, v[3] * inv);
    __nv_bfloat162 o45 = __floats2bfloat162_rn(v[4] * inv, v[5] * inv);
    __nv_bfloat162 o67 = __floats2bfloat162_rn(v[6] * inv, v[7] * inv);
    uint2 pa, pb;
    pa.x = *(u32*)&o01; pa.y = *(u32*)&o23;
    pb.x = *(u32*)&o45; pb.y = *(u32*)&o67;
    *(uint2*)(orow + t * 4) = pa;
    *(uint2*)(orow + (t + 256) * 4) = pb;
}

// ---------------------------------------------------------------------------
extern "C" void kernel_launch(void* const* d_in, const int* in_sizes, int n_in,
                              void* d_out, int out_size) {
    const float* x    = (const float*)d_in[0];
    const float* ln_g = (const float*)d_in[1];
    const float* ln_b = (const float*)d_in[2];
    const float* Wq   = (const float*)d_in[3];
    const float* bq   = (const float*)d_in[4];
    const float* Wk   = (const float*)d_in[5];
    const float* bk   = (const float*)d_in[6];  (void)bk;
    float* out = (float*)d_out;

    const int SMEM_DYN = NSTAGE * STAGE_BYTES * 2;   // 61440
    cudaFuncSetAttribute(mma_gemm<false, true >, cudaFuncAttributeMaxDynamicSharedMemorySize, SMEM_DYN);
    cudaFuncSetAttribute(mma_gemm<false, false>, cudaFuncAttributeMaxDynamicSharedMemorySize, SMEM_DYN);
    cudaFuncSetAttribute(mma_gemm<true,  false>, cudaFuncAttributeMaxDynamicSharedMemorySize, SMEM_DYN);

    __nv_bfloat16 *p_xn, *p_wqT, *p_wkT, *p_mt, *p_g, *p_pb, *p_xt;
    float* p_p;
    cudaGetSymbolAddress((void**)&p_xn,  g_xn);
    cudaGetSymbolAddress((void**)&p_wqT, g_wqT);
    cudaGetSymbolAddress((void**)&p_wkT, g_wkT);
    cudaGetSymbolAddress((void**)&p_mt,  g_mt);
    cudaGetSymbolAddress((void**)&p_g,   g_g);
    cudaGetSymbolAddress((void**)&p_p,   g_p);
    cudaGetSymbolAddress((void**)&p_pb,  g_pb);
    cudaGetSymbolAddress((void**)&p_xt,  g_xt);

    w_kernel<<<DD, 256>>>(Wk, bq);
    ln_kernel<<<MTOT, 256>>>(x, ln_g, ln_b);
    convwT_kernel<<<dim3(DD / 32, DD / 32), 256>>>(Wq, Wk);
    transpose_kernel<<<dim3(SS / 32, DD / 32, BB), 256>>>(x);

    // MT[j,i] = sum_m WkT[j,m] * WqT[i,m]  (= M[i,j], M = Wq^T Wk)
    mma_gemm<false, true><<<dim3(DD / 128, DD / 128, 1), 256, SMEM_DYN>>>(
        p_wkT, p_wqT, p_mt, nullptr, DD, DD, 0, 0, 0);

    // G = xn @ M   (G[s,j] = sum_i xn[s,i] * MT[j,i]),  M=16384, N=768, K=768
    mma_gemm<false, true><<<dim3(DD / 128, MTOT / 128, 1), 256, SMEM_DYN>>>(
        p_xn, p_mt, p_g, nullptr, DD, DD, 0, 0, 0);

    // scores = G @ xn^T  (per batch), unscaled; softmax applies alpha & +c
    mma_gemm<false, false><<<dim3(SS / 128, SS / 128, BB), 256, SMEM_DYN>>>(
        p_g, p_xn, p_p, nullptr, SS, DD,
        (long)SS * DD, (long)SS * DD, (long)SS * SS);

    softmax_kernel<<<BB * SS, 256>>>();

    // out = P @ x + x   (A = P bf16 [S,S], B = x^T bf16 [D,S])
    mma_gemm<true, false><<<dim3(DD / 128, SS / 128, BB), 256, SMEM_DYN>>>(
        p_pb, p_xt, out, x, DD, SS,
        (long)SS * SS, (long)DD * SS, (long)SS * DD);
}

// round 9
// speedup vs baseline: 1.2465x; 1.0128x over previous
#include <cuda_runtime.h>
#include <cuda_bf16.h>

#define DD   768
#define BB   8
#define SS   2048
#define MTOT (BB * SS)
#define BK   32
#define PITCH 40                        // bf16 per smem row (80B, conflict-free)
#define STAGE_BYTES (128 * PITCH * 2)   // 10240 per operand tile
#define NSTAGE 3
#define ALPHA 0.036084391824351615f     // 1/sqrt(768)

typedef unsigned int u32;

// ---------------------------------------------------------------------------
// Device scratch (no allocations allowed)
// ---------------------------------------------------------------------------
__device__ __nv_bfloat16 g_xn [(size_t)MTOT * DD];      // LN output (bf16)
__device__ __nv_bfloat16 g_wqT[(size_t)DD * DD];        // Wq^T bf16 [i][m]
__device__ __nv_bfloat16 g_wkT[(size_t)DD * DD];        // Wk^T bf16 [j][m]
__device__ __nv_bfloat16 g_mt [(size_t)DD * DD];        // M^T bf16, MT[j][i]=M[i][j]
__device__ __nv_bfloat16 g_g  [(size_t)MTOT * DD];      // G = xn @ M  bf16
__device__ __nv_bfloat16 g_pl [(size_t)BB * SS * SS];   // logits bf16 (scaled, +c)
__device__ __nv_bfloat16 g_pb [(size_t)BB * SS * SS];   // probs bf16
__device__ __nv_bfloat16 g_xt [(size_t)BB * DD * SS];   // x^T bf16 [b][d][s]
__device__ float         g_w  [DD];                     // w = Wk^T bq
__device__ float         g_c  [MTOT];                   // c_row = xn_row . w

// ---------------------------------------------------------------------------
__device__ __forceinline__ u32 smem_u32(const void* p) {
    u32 a;
    asm("{ .reg .u64 t; cvta.to.shared.u64 t, %1; cvt.u32.u64 %0, t; }" : "=r"(a) : "l"(p));
    return a;
}
#define CP_ASYNC16(sa, ga) \
    asm volatile("cp.async.cg.shared.global [%0], [%1], 16;" :: "r"(sa), "l"(ga) : "memory")
#define CP_COMMIT()  asm volatile("cp.async.commit_group;" ::: "memory")
#define CP_WAIT(n)   asm volatile("cp.async.wait_group %0;" :: "n"(n) : "memory")
#define LDSM_X4(r0, r1, r2, r3, addr) \
    asm volatile("ldmatrix.sync.aligned.m8n8.x4.shared.b16 {%0,%1,%2,%3}, [%4];" \
        : "=r"(r0), "=r"(r1), "=r"(r2), "=r"(r3) : "r"(addr))

__device__ __forceinline__ void mma16816(float* c, const u32* a, u32 b0, u32 b1) {
    asm volatile(
        "mma.sync.aligned.m16n8k16.row.col.f32.bf16.bf16.f32 "
        "{%0,%1,%2,%3}, {%4,%5,%6,%7}, {%8,%9}, {%0,%1,%2,%3};"
        : "+f"(c[0]), "+f"(c[1]), "+f"(c[2]), "+f"(c[3])
        : "r"(a[0]), "r"(a[1]), "r"(a[2]), "r"(a[3]), "r"(b0), "r"(b1));
}

// ---------------------------------------------------------------------------
// HMMA GEMM (R5-proven mainloop): C[m,n] = sum_k A[m,k]*B[n,k]
// MODE 0: bf16 out plain          (MT, G)
// MODE 1: bf16 out, (v+c[col])*ALPHA  (scores -> logits)
// MODE 2: fp32 out + resid        (av output)
// ---------------------------------------------------------------------------
template <int MODE>
__global__ __launch_bounds__(256) void mma_gemm(
    const __nv_bfloat16* __restrict__ A, const __nv_bfloat16* __restrict__ B,
    void* __restrict__ Cv,
    const float* __restrict__ extra,       // MODE1: c vec (per batch); MODE2: resid
    int N, int K, long aStride, long bStride, long cStride)
{
    extern __shared__ char smem[];
    const u32 aTile0 = smem_u32(smem);
    const u32 bTile0 = aTile0 + NSTAGE * STAGE_BYTES;

    const int tid = threadIdx.x;
    const int wid = tid >> 5, lane = tid & 31;
    const int wm = wid & 3, wn = wid >> 2;          // 4 x 2 warp grid
    const int g = lane >> 2, t = lane & 3;          // mma fragment coords
    const int m0 = blockIdx.y * 128, n0 = blockIdx.x * 128;
    const int z = blockIdx.z;

    A += (size_t)z * aStride + (size_t)m0 * K;
    B += (size_t)z * bStride + (size_t)n0 * K;

    const int NC = K / BK;
    const int r0 = tid >> 2, c0 = (tid & 3) * 8;
    const int r1 = r0 + 64;
    const u32 sA0 = aTile0 + r0 * (PITCH * 2) + c0 * 2;
    const u32 sA1 = aTile0 + r1 * (PITCH * 2) + c0 * 2;
    const u32 sB0 = bTile0 + r0 * (PITCH * 2) + c0 * 2;
    const u32 sB1 = bTile0 + r1 * (PITCH * 2) + c0 * 2;

    const int lr = lane & 15, lk = (lane >> 4) * 8;
    const u32 aLds = aTile0 + (wm * 32 + lr) * (PITCH * 2) + lk * 2;
    const u32 bLds = bTile0 + (wn * 64 + lr) * (PITCH * 2) + lk * 2;

    float acc[2][8][4];
    #pragma unroll
    for (int mt = 0; mt < 2; mt++)
        #pragma unroll
        for (int nt = 0; nt < 8; nt++)
            #pragma unroll
            for (int i = 0; i < 4; i++) acc[mt][nt][i] = 0.f;

    #pragma unroll
    for (int s = 0; s < 2; s++) {
        const __nv_bfloat16* Ak = A + (size_t)s * BK;
        const __nv_bfloat16* Bk = B + (size_t)s * BK;
        const u32 so = s * STAGE_BYTES;
        CP_ASYNC16(sA0 + so, Ak + (size_t)r0 * K + c0);
        CP_ASYNC16(sA1 + so, Ak + (size_t)r1 * K + c0);
        CP_ASYNC16(sB0 + so, Bk + (size_t)r0 * K + c0);
        CP_ASYNC16(sB1 + so, Bk + (size_t)r1 * K + c0);
        CP_COMMIT();
    }

    int st = 0;
    for (int c = 0; c < NC; ++c) {
        CP_WAIT(1);
        __syncthreads();

        if (c + 2 < NC) {
            const int ps = (st + 2 >= NSTAGE) ? st + 2 - NSTAGE : st + 2;
            const __nv_bfloat16* Ak = A + (size_t)(c + 2) * BK;
            const __nv_bfloat16* Bk = B + (size_t)(c + 2) * BK;
            const u32 so = ps * STAGE_BYTES;
            CP_ASYNC16(sA0 + so, Ak + (size_t)r0 * K + c0);
            CP_ASYNC16(sA1 + so, Ak + (size_t)r1 * K + c0);
            CP_ASYNC16(sB0 + so, Bk + (size_t)r0 * K + c0);
            CP_ASYNC16(sB1 + so, Bk + (size_t)r1 * K + c0);
        }
        CP_COMMIT();

        const u32 so = st * STAGE_BYTES;
        #pragma unroll
        for (int kk = 0; kk < 2; kk++) {
            u32 a[2][4], b[4][4];
            #pragma unroll
            for (int mt = 0; mt < 2; mt++)
                LDSM_X4(a[mt][0], a[mt][1], a[mt][2], a[mt][3],
                        aLds + so + mt * (16 * PITCH * 2) + kk * 32);
            #pragma unroll
            for (int np = 0; np < 4; np++)
                LDSM_X4(b[np][0], b[np][1], b[np][2], b[np][3],
                        bLds + so + np * (16 * PITCH * 2) + kk * 32);
            #pragma unroll
            for (int mt = 0; mt < 2; mt++)
                #pragma unroll
                for (int nt = 0; nt < 8; nt++)
                    mma16816(acc[mt][nt], a[mt], b[nt >> 1][nt & 1], b[nt >> 1][2 + (nt & 1)]);
        }
        st = (st + 1 >= NSTAGE) ? 0 : st + 1;
    }

    // Epilogue
    #pragma unroll
    for (int mt = 0; mt < 2; mt++) {
        #pragma unroll
        for (int nt = 0; nt < 8; nt++) {
            const int row = m0 + wm * 32 + mt * 16 + g;
            const int col = n0 + wn * 64 + nt * 8 + 2 * t;
            float v0 = acc[mt][nt][0], v1 = acc[mt][nt][1];
            float v2 = acc[mt][nt][2], v3 = acc[mt][nt][3];
            if (MODE == 0) {
                __nv_bfloat16* Cb = (__nv_bfloat16*)Cv + (size_t)z * cStride;
                *(__nv_bfloat162*)(Cb + (size_t)row * N + col) = __floats2bfloat162_rn(v0, v1);
                *(__nv_bfloat162*)(Cb + (size_t)(row + 8) * N + col) = __floats2bfloat162_rn(v2, v3);
            } else if (MODE == 1) {
                const float* cv = extra + (size_t)z * SS;
                float ca = cv[col], cb = cv[col + 1];
                v0 = (v0 + ca) * ALPHA; v1 = (v1 + cb) * ALPHA;
                v2 = (v2 + ca) * ALPHA; v3 = (v3 + cb) * ALPHA;
                __nv_bfloat16* Cb = (__nv_bfloat16*)Cv + (size_t)z * cStride;
                *(__nv_bfloat162*)(Cb + (size_t)row * N + col) = __floats2bfloat162_rn(v0, v1);
                *(__nv_bfloat162*)(Cb + (size_t)(row + 8) * N + col) = __floats2bfloat162_rn(v2, v3);
            } else {
                float* Cf = (float*)Cv + (size_t)z * cStride;
                const float* R = extra + (size_t)z * cStride;
                float2 ra = *(const float2*)(R + (size_t)row * N + col);
                float2 rb = *(const float2*)(R + (size_t)(row + 8) * N + col);
                v0 += ra.x; v1 += ra.y; v2 += rb.x; v3 += rb.y;
                *(float2*)(Cf + (size_t)row * N + col) = make_float2(v0, v1);
                *(float2*)(Cf + (size_t)(row + 8) * N + col) = make_float2(v2, v3);
            }
        }
    }
}

// ---------------------------------------------------------------------------
// Reductions
// ---------------------------------------------------------------------------
__device__ __forceinline__ float blockReduceSum(float v) {
    __shared__ float sh[32];
    int lane = threadIdx.x & 31, wid = threadIdx.x >> 5;
    #pragma unroll
    for (int o = 16; o; o >>= 1) v += __shfl_down_sync(0xffffffffu, v, o);
    if (lane == 0) sh[wid] = v;
    __syncthreads();
    float r = (threadIdx.x < (blockDim.x >> 5)) ? sh[threadIdx.x] : 0.f;
    if (wid == 0) {
        #pragma unroll
        for (int o = 16; o; o >>= 1) r += __shfl_down_sync(0xffffffffu, r, o);
        if (lane == 0) sh[0] = r;
    }
    __syncthreads();
    float out = sh[0];
    __syncthreads();
    return out;
}
__device__ __forceinline__ float blockReduceMax(float v) {
    __shared__ float sh[32];
    int lane = threadIdx.x & 31, wid = threadIdx.x >> 5;
    #pragma unroll
    for (int o = 16; o; o >>= 1) v = fmaxf(v, __shfl_down_sync(0xffffffffu, v, o));
    if (lane == 0) sh[wid] = v;
    __syncthreads();
    float r = (threadIdx.x < (blockDim.x >> 5)) ? sh[threadIdx.x] : -3.4e38f;
    if (wid == 0) {
        #pragma unroll
        for (int o = 16; o; o >>= 1) r = fmaxf(r, __shfl_down_sync(0xffffffffu, r, o));
        if (lane == 0) sh[0] = r;
    }
    __syncthreads();
    float out = sh[0];
    __syncthreads();
    return out;
}

// w[d] = sum_j bq[j] * Wk[j,d]
__global__ __launch_bounds__(256) void w_kernel(const float* __restrict__ Wk,
                                                const float* __restrict__ bq) {
    int d = blockIdx.x, t = threadIdx.x;
    float s = 0.f;
    for (int j = t; j < DD; j += 256) s += bq[j] * Wk[(size_t)j * DD + d];
    s = blockReduceSum(s);
    if (t == 0) g_w[d] = s;
}

// LayerNorm -> bf16, plus c_row = xn_row . w
__global__ __launch_bounds__(256) void ln_kernel(const float* __restrict__ x,
                                                 const float* __restrict__ g,
                                                 const float* __restrict__ b) {
    int row = blockIdx.x, t = threadIdx.x;
    const float* xr = x + (size_t)row * DD;
    float v[3];
    #pragma unroll
    for (int i = 0; i < 3; i++) v[i] = xr[t + i * 256];
    float mean = blockReduceSum(v[0] + v[1] + v[2]) * (1.0f / DD);
    float q = 0.f;
    #pragma unroll
    for (int i = 0; i < 3; i++) { float d = v[i] - mean; q += d * d; }
    float inv = rsqrtf(blockReduceSum(q) * (1.0f / DD) + 1e-5f);
    __nv_bfloat16* o = g_xn + (size_t)row * DD;
    float cdot = 0.f;
    #pragma unroll
    for (int i = 0; i < 3; i++) {
        int c = t + i * 256;
        float xv = (v[i] - mean) * inv * g[c] + b[c];
        o[c] = __float2bfloat16_rn(xv);
        cdot += xv * g_w[c];
    }
    cdot = blockReduceSum(cdot);
    if (t == 0) g_c[row] = cdot;
}

// Transpose W fp32 [m][i] -> bf16 [i][m] for both weights
__global__ __launch_bounds__(256) void convwT_kernel(const float* __restrict__ Wq,
                                                     const float* __restrict__ Wk) {
    __shared__ float tq[32][33];
    __shared__ float tk[32][33];
    int m0 = blockIdx.x * 32, i0 = blockIdx.y * 32;
    int tx = threadIdx.x & 31, ty = threadIdx.x >> 5;
    #pragma unroll
    for (int r = 0; r < 4; r++) {
        tq[ty + r * 8][tx] = Wq[(size_t)(m0 + ty + r * 8) * DD + i0 + tx];
        tk[ty + r * 8][tx] = Wk[(size_t)(m0 + ty + r * 8) * DD + i0 + tx];
    }
    __syncthreads();
    #pragma unroll
    for (int r = 0; r < 4; r++) {
        g_wqT[(size_t)(i0 + ty + r * 8) * DD + m0 + tx] = __float2bfloat16_rn(tq[tx][ty + r * 8]);
        g_wkT[(size_t)(i0 + ty + r * 8) * DD + m0 + tx] = __float2bfloat16_rn(tk[tx][ty + r * 8]);
    }
}

// x [b][s][d] fp32 -> g_xt [b][d][s] bf16, float4-vectorized
__global__ __launch_bounds__(256) void transpose_kernel(const float* __restrict__ x) {
    __shared__ float tile[32][36];
    int b = blockIdx.z;
    int s0 = blockIdx.x * 32, d0 = blockIdx.y * 32;
    // load: 8 float4-lanes x 32 rows = 256 threads, one float4 each
    int f4 = threadIdx.x & 7, row = threadIdx.x >> 3;
    float4 v = *(const float4*)(x + (size_t)b * SS * DD + (size_t)(s0 + row) * DD + d0 + f4 * 4);
    tile[row][f4 * 4 + 0] = v.x; tile[row][f4 * 4 + 1] = v.y;
    tile[row][f4 * 4 + 2] = v.z; tile[row][f4 * 4 + 3] = v.w;
    __syncthreads();
    // store: 16 bf16x2-lanes x 16 d-rows, 2 iterations
    int sx = threadIdx.x & 15, dr = threadIdx.x >> 4;   // sx: s-pair, dr: d row
    #pragma unroll
    for (int it = 0; it < 2; it++) {
        int d = dr + it * 16;
        __nv_bfloat162 o = __floats2bfloat162_rn(tile[sx * 2][d], tile[sx * 2 + 1][d]);
        *(__nv_bfloat162*)(g_xt + (size_t)b * DD * SS + (size_t)(d0 + d) * SS + s0 + sx * 2) = o;
    }
}

// softmax over bf16 logits -> bf16 probs
__global__ __launch_bounds__(256) void softmax_kernel() {
    const __nv_bfloat16* row = g_pl + (size_t)blockIdx.x * SS;
    __nv_bfloat16* orow = g_pb + (size_t)blockIdx.x * SS;
    int t = threadIdx.x;
    uint4 pk = *(const uint4*)(row + t * 8);
    float v[8];
    {
        __nv_bfloat162 h0 = *(__nv_bfloat162*)&pk.x;
        __nv_bfloat162 h1 = *(__nv_bfloat162*)&pk.y;
        __nv_bfloat162 h2 = *(__nv_bfloat162*)&pk.z;
        __nv_bfloat162 h3 = *(__nv_bfloat162*)&pk.w;
        v[0] = __low2float(h0); v[1] = __high2float(h0);
        v[2] = __low2float(h1); v[3] = __high2float(h1);
        v[4] = __low2float(h2); v[5] = __high2float(h2);
        v[6] = __low2float(h3); v[7] = __high2float(h3);
    }
    float m = v[0];
    #pragma unroll
    for (int i = 1; i < 8; i++) m = fmaxf(m, v[i]);
    m = blockReduceMax(m);
    float s = 0.f;
    #pragma unroll
    for (int i = 0; i < 8; i++) { v[i] = __expf(v[i] - m); s += v[i]; }
    s = blockReduceSum(s);
    float inv = 1.0f / s;
    __nv_bfloat162 o01 = __floats2bfloat162_rn(v[0] * inv, v[1] * inv);
    __nv_bfloat162 o23 = __floats2bfloat162_rn(v[2] * inv, v[3] * inv);
    __nv_bfloat162 o45 = __floats2bfloat162_rn(v[4] * inv, v[5] * inv);
    __nv_bfloat162 o67 = __floats2bfloat162_rn(v[6] * inv, v[7] * inv);
    uint4 po;
    po.x = *(u32*)&o01; po.y = *(u32*)&o23;
    po.z = *(u32*)&o45; po.w = *(u32*)&o67;
    *(uint4*)(orow + t * 8) = po;
}

// ---------------------------------------------------------------------------
extern "C" void kernel_launch(void* const* d_in, const int* in_sizes, int n_in,
                              void* d_out, int out_size) {
    const float* x    = (const float*)d_in[0];
    const float* ln_g = (const float*)d_in[1];
    const float* ln_b = (const float*)d_in[2];
    const float* Wq   = (const float*)d_in[3];
    const float* bq   = (const float*)d_in[4];
    const float* Wk   = (const float*)d_in[5];
    const float* bk   = (const float*)d_in[6];  (void)bk;
    float* out = (float*)d_out;

    const int SMEM_DYN = NSTAGE * STAGE_BYTES * 2;   // 61440
    cudaFuncSetAttribute(mma_gemm<0>, cudaFuncAttributeMaxDynamicSharedMemorySize, SMEM_DYN);
    cudaFuncSetAttribute(mma_gemm<1>, cudaFuncAttributeMaxDynamicSharedMemorySize, SMEM_DYN);
    cudaFuncSetAttribute(mma_gemm<2>, cudaFuncAttributeMaxDynamicSharedMemorySize, SMEM_DYN);

    __nv_bfloat16 *p_xn, *p_wqT, *p_wkT, *p_mt, *p_g, *p_pl, *p_pb, *p_xt;
    float* p_c;
    cudaGetSymbolAddress((void**)&p_xn,  g_xn);
    cudaGetSymbolAddress((void**)&p_wqT, g_wqT);
    cudaGetSymbolAddress((void**)&p_wkT, g_wkT);
    cudaGetSymbolAddress((void**)&p_mt,  g_mt);
    cudaGetSymbolAddress((void**)&p_g,   g_g);
    cudaGetSymbolAddress((void**)&p_pl,  g_pl);
    cudaGetSymbolAddress((void**)&p_pb,  g_pb);
    cudaGetSymbolAddress((void**)&p_xt,  g_xt);
    cudaGetSymbolAddress((void**)&p_c,   g_c);

    w_kernel<<<DD, 256>>>(Wk, bq);
    ln_kernel<<<MTOT, 256>>>(x, ln_g, ln_b);
    convwT_kernel<<<dim3(DD / 32, DD / 32), 256>>>(Wq, Wk);
    transpose_kernel<<<dim3(SS / 32, DD / 32, BB), 256>>>(x);

    // MT[j,i] = sum_m WkT[j,m] * WqT[i,m]  (= M[i,j], M = Wq^T Wk)
    mma_gemm<0><<<dim3(DD / 128, DD / 128, 1), 256, SMEM_DYN>>>(
        p_wkT, p_wqT, p_mt, nullptr, DD, DD, 0, 0, 0);

    // G = xn @ M   (M=16384, N=768, K=768)
    mma_gemm<0><<<dim3(DD / 128, MTOT / 128, 1), 256, SMEM_DYN>>>(
        p_xn, p_mt, p_g, nullptr, DD, DD, 0, 0, 0);

    // logits = (G @ xn^T + c_t) * alpha, stored bf16
    mma_gemm<1><<<dim3(SS / 128, SS / 128, BB), 256, SMEM_DYN>>>(
        p_g, p_xn, p_pl, p_c, SS, DD,
        (long)SS * DD, (long)SS * DD, (long)SS * SS);

    softmax_kernel<<<BB * SS, 256>>>();

    // out = P @ x + x   (A = P bf16 [S,S], B = x^T bf16 [D,S])
    mma_gemm<2><<<dim3(DD / 128, SS / 128, BB), 256, SMEM_DYN>>>(
        p_pb, p_xt, out, x, DD, SS,
        (long)SS * SS, (long)DD * SS, (long)SS * DD);
}

// round 10
// speedup vs baseline: 1.2858x; 1.0315x over previous
#include <cuda_runtime.h>
#include <cuda_bf16.h>

#define DD   768
#define BB   8
#define SS   2048
#define MTOT (BB * SS)
#define BK   32
#define PITCH 40                        // bf16 per smem row (80B, conflict-free)
#define STAGE_BYTES (128 * PITCH * 2)   // 10240 per operand tile
#define NSTAGE 3
#define ALPHA 0.036084391824351615f     // 1/sqrt(768)

typedef unsigned int u32;

// ---------------------------------------------------------------------------
// Device scratch (no allocations allowed)
// ---------------------------------------------------------------------------
__device__ __nv_bfloat16 g_xn [(size_t)MTOT * DD];      // LN output (bf16)
__device__ __nv_bfloat16 g_wqT[(size_t)DD * DD];        // Wq^T bf16 [i][m]
__device__ __nv_bfloat16 g_wkT[(size_t)DD * DD];        // Wk^T bf16 [j][m]
__device__ __nv_bfloat16 g_mt [(size_t)DD * DD];        // M^T bf16, MT[j][i]=M[i][j]
__device__ __nv_bfloat16 g_g  [(size_t)MTOT * DD];      // G = xn @ M  bf16
__device__ __nv_bfloat16 g_pb [(size_t)BB * SS * SS];   // p_unnorm = exp(logit) bf16
__device__ __nv_bfloat16 g_xt [(size_t)BB * DD * SS];   // x^T bf16 [b][d][s]
__device__ float         g_w  [DD];                     // w = Wk^T bq
__device__ float         g_c  [MTOT];                   // c_row = xn_row . w
__device__ float         g_ps [(size_t)MTOT * 16];      // per-(row, ntile) partial sums
__device__ float         g_si [MTOT];                   // 1 / row sum

// ---------------------------------------------------------------------------
__device__ __forceinline__ u32 smem_u32(const void* p) {
    u32 a;
    asm("{ .reg .u64 t; cvta.to.shared.u64 t, %1; cvt.u32.u64 %0, t; }" : "=r"(a) : "l"(p));
    return a;
}
#define CP_ASYNC16(sa, ga) \
    asm volatile("cp.async.cg.shared.global [%0], [%1], 16;" :: "r"(sa), "l"(ga) : "memory")
#define CP_COMMIT()  asm volatile("cp.async.commit_group;" ::: "memory")
#define CP_WAIT(n)   asm volatile("cp.async.wait_group %0;" :: "n"(n) : "memory")
#define LDSM_X4(r0, r1, r2, r3, addr) \
    asm volatile("ldmatrix.sync.aligned.m8n8.x4.shared.b16 {%0,%1,%2,%3}, [%4];" \
        : "=r"(r0), "=r"(r1), "=r"(r2), "=r"(r3) : "r"(addr))

__device__ __forceinline__ void mma16816(float* c, const u32* a, u32 b0, u32 b1) {
    asm volatile(
        "mma.sync.aligned.m16n8k16.row.col.f32.bf16.bf16.f32 "
        "{%0,%1,%2,%3}, {%4,%5,%6,%7}, {%8,%9}, {%0,%1,%2,%3};"
        : "+f"(c[0]), "+f"(c[1]), "+f"(c[2]), "+f"(c[3])
        : "r"(a[0]), "r"(a[1]), "r"(a[2]), "r"(a[3]), "r"(b0), "r"(b1));
}

// ---------------------------------------------------------------------------
// HMMA GEMM (R5-proven mainloop): C[m,n] = sum_k A[m,k]*B[n,k]
// MODE 0: bf16 out plain                         (MT, G)
// MODE 1: p = exp((v+c[col])*ALPHA) bf16 out + per-row partial sums (scores)
// MODE 2: fp32 out: v * g_si[row] + resid        (av output)
// ---------------------------------------------------------------------------
template <int MODE>
__global__ __launch_bounds__(256) void mma_gemm(
    const __nv_bfloat16* __restrict__ A, const __nv_bfloat16* __restrict__ B,
    void* __restrict__ Cv,
    const float* __restrict__ extra,       // MODE1: c vec (per batch); MODE2: resid
    int N, int K, long aStride, long bStride, long cStride)
{
    extern __shared__ char smem[];
    const u32 aTile0 = smem_u32(smem);
    const u32 bTile0 = aTile0 + NSTAGE * STAGE_BYTES;

    const int tid = threadIdx.x;
    const int wid = tid >> 5, lane = tid & 31;
    const int wm = wid & 3, wn = wid >> 2;          // 4 x 2 warp grid
    const int g = lane >> 2, t = lane & 3;          // mma fragment coords
    const int m0 = blockIdx.y * 128, n0 = blockIdx.x * 128;
    const int z = blockIdx.z;

    A += (size_t)z * aStride + (size_t)m0 * K;
    B += (size_t)z * bStride + (size_t)n0 * K;

    const int NC = K / BK;
    const int r0 = tid >> 2, c0 = (tid & 3) * 8;
    const int r1 = r0 + 64;
    const u32 sA0 = aTile0 + r0 * (PITCH * 2) + c0 * 2;
    const u32 sA1 = aTile0 + r1 * (PITCH * 2) + c0 * 2;
    const u32 sB0 = bTile0 + r0 * (PITCH * 2) + c0 * 2;
    const u32 sB1 = bTile0 + r1 * (PITCH * 2) + c0 * 2;

    const int lr = lane & 15, lk = (lane >> 4) * 8;
    const u32 aLds = aTile0 + (wm * 32 + lr) * (PITCH * 2) + lk * 2;
    const u32 bLds = bTile0 + (wn * 64 + lr) * (PITCH * 2) + lk * 2;

    float acc[2][8][4];
    #pragma unroll
    for (int mt = 0; mt < 2; mt++)
        #pragma unroll
        for (int nt = 0; nt < 8; nt++)
            #pragma unroll
            for (int i = 0; i < 4; i++) acc[mt][nt][i] = 0.f;

    #pragma unroll
    for (int s = 0; s < 2; s++) {
        const __nv_bfloat16* Ak = A + (size_t)s * BK;
        const __nv_bfloat16* Bk = B + (size_t)s * BK;
        const u32 so = s * STAGE_BYTES;
        CP_ASYNC16(sA0 + so, Ak + (size_t)r0 * K + c0);
        CP_ASYNC16(sA1 + so, Ak + (size_t)r1 * K + c0);
        CP_ASYNC16(sB0 + so, Bk + (size_t)r0 * K + c0);
        CP_ASYNC16(sB1 + so, Bk + (size_t)r1 * K + c0);
        CP_COMMIT();
    }

    int st = 0;
    for (int c = 0; c < NC; ++c) {
        CP_WAIT(1);
        __syncthreads();

        if (c + 2 < NC) {
            const int ps = (st + 2 >= NSTAGE) ? st + 2 - NSTAGE : st + 2;
            const __nv_bfloat16* Ak = A + (size_t)(c + 2) * BK;
            const __nv_bfloat16* Bk = B + (size_t)(c + 2) * BK;
            const u32 so = ps * STAGE_BYTES;
            CP_ASYNC16(sA0 + so, Ak + (size_t)r0 * K + c0);
            CP_ASYNC16(sA1 + so, Ak + (size_t)r1 * K + c0);
            CP_ASYNC16(sB0 + so, Bk + (size_t)r0 * K + c0);
            CP_ASYNC16(sB1 + so, Bk + (size_t)r1 * K + c0);
        }
        CP_COMMIT();

        const u32 so = st * STAGE_BYTES;
        #pragma unroll
        for (int kk = 0; kk < 2; kk++) {
            u32 a[2][4], b[4][4];
            #pragma unroll
            for (int mt = 0; mt < 2; mt++)
                LDSM_X4(a[mt][0], a[mt][1], a[mt][2], a[mt][3],
                        aLds + so + mt * (16 * PITCH * 2) + kk * 32);
            #pragma unroll
            for (int np = 0; np < 4; np++)
                LDSM_X4(b[np][0], b[np][1], b[np][2], b[np][3],
                        bLds + so + np * (16 * PITCH * 2) + kk * 32);
            #pragma unroll
            for (int mt = 0; mt < 2; mt++)
                #pragma unroll
                for (int nt = 0; nt < 8; nt++)
                    mma16816(acc[mt][nt], a[mt], b[nt >> 1][nt & 1], b[nt >> 1][2 + (nt & 1)]);
        }
        st = (st + 1 >= NSTAGE) ? 0 : st + 1;
    }

    // Epilogue
    if (MODE == 0) {
        #pragma unroll
        for (int mt = 0; mt < 2; mt++)
            #pragma unroll
            for (int nt = 0; nt < 8; nt++) {
                const int row = m0 + wm * 32 + mt * 16 + g;
                const int col = n0 + wn * 64 + nt * 8 + 2 * t;
                __nv_bfloat16* Cb = (__nv_bfloat16*)Cv + (size_t)z * cStride;
                *(__nv_bfloat162*)(Cb + (size_t)row * N + col) =
                    __floats2bfloat162_rn(acc[mt][nt][0], acc[mt][nt][1]);
                *(__nv_bfloat162*)(Cb + (size_t)(row + 8) * N + col) =
                    __floats2bfloat162_rn(acc[mt][nt][2], acc[mt][nt][3]);
            }
    } else if (MODE == 1) {
        // p = exp((v + c[col]) * ALPHA); also per-row partial sums.
        float rs[2][2] = {{0.f, 0.f}, {0.f, 0.f}};   // [mt][row half]
        const float* cv = extra + (size_t)z * SS;
        #pragma unroll
        for (int mt = 0; mt < 2; mt++)
            #pragma unroll
            for (int nt = 0; nt < 8; nt++) {
                const int row = m0 + wm * 32 + mt * 16 + g;
                const int col = n0 + wn * 64 + nt * 8 + 2 * t;
                float ca = cv[col], cb = cv[col + 1];
                float e0 = __expf((acc[mt][nt][0] + ca) * ALPHA);
                float e1 = __expf((acc[mt][nt][1] + cb) * ALPHA);
                float e2 = __expf((acc[mt][nt][2] + ca) * ALPHA);
                float e3 = __expf((acc[mt][nt][3] + cb) * ALPHA);
                rs[mt][0] += e0 + e1;
                rs[mt][1] += e2 + e3;
                __nv_bfloat16* Cb = (__nv_bfloat16*)Cv + (size_t)z * cStride;
                *(__nv_bfloat162*)(Cb + (size_t)row * N + col) = __floats2bfloat162_rn(e0, e1);
                *(__nv_bfloat162*)(Cb + (size_t)(row + 8) * N + col) = __floats2bfloat162_rn(e2, e3);
            }
        // reduce over the 4 t-lanes (deterministic butterfly)
        #pragma unroll
        for (int mt = 0; mt < 2; mt++)
            #pragma unroll
            for (int h = 0; h < 2; h++) {
                rs[mt][h] += __shfl_xor_sync(0xffffffffu, rs[mt][h], 1);
                rs[mt][h] += __shfl_xor_sync(0xffffffffu, rs[mt][h], 2);
            }
        __syncthreads();                      // done with mainloop smem; reuse
        float* sRow = (float*)smem;           // [128 rows][2 wn]
        if (t == 0) {
            #pragma unroll
            for (int mt = 0; mt < 2; mt++) {
                sRow[(wm * 32 + mt * 16 + g) * 2 + wn]     = rs[mt][0];
                sRow[(wm * 32 + mt * 16 + 8 + g) * 2 + wn] = rs[mt][1];
            }
        }
        __syncthreads();
        if (tid < 128) {
            float s = sRow[tid * 2] + sRow[tid * 2 + 1];
            g_ps[((size_t)z * SS + m0 + tid) * 16 + blockIdx.x] = s;
        }
    } else {
        float invs[2][2];
        #pragma unroll
        for (int mt = 0; mt < 2; mt++) {
            const int row = m0 + wm * 32 + mt * 16 + g;
            invs[mt][0] = g_si[(size_t)z * SS + row];
            invs[mt][1] = g_si[(size_t)z * SS + row + 8];
        }
        #pragma unroll
        for (int mt = 0; mt < 2; mt++)
            #pragma unroll
            for (int nt = 0; nt < 8; nt++) {
                const int row = m0 + wm * 32 + mt * 16 + g;
                const int col = n0 + wn * 64 + nt * 8 + 2 * t;
                float* Cf = (float*)Cv + (size_t)z * cStride;
                const float* R = extra + (size_t)z * cStride;
                float2 ra = *(const float2*)(R + (size_t)row * N + col);
                float2 rb = *(const float2*)(R + (size_t)(row + 8) * N + col);
                float v0 = acc[mt][nt][0] * invs[mt][0] + ra.x;
                float v1 = acc[mt][nt][1] * invs[mt][0] + ra.y;
                float v2 = acc[mt][nt][2] * invs[mt][1] + rb.x;
                float v3 = acc[mt][nt][3] * invs[mt][1] + rb.y;
                *(float2*)(Cf + (size_t)row * N + col) = make_float2(v0, v1);
                *(float2*)(Cf + (size_t)(row + 8) * N + col) = make_float2(v2, v3);
            }
    }
}

// ---------------------------------------------------------------------------
// Reductions
// ---------------------------------------------------------------------------
__device__ __forceinline__ float blockReduceSum(float v) {
    __shared__ float sh[32];
    int lane = threadIdx.x & 31, wid = threadIdx.x >> 5;
    #pragma unroll
    for (int o = 16; o; o >>= 1) v += __shfl_down_sync(0xffffffffu, v, o);
    if (lane == 0) sh[wid] = v;
    __syncthreads();
    float r = (threadIdx.x < (blockDim.x >> 5)) ? sh[threadIdx.x] : 0.f;
    if (wid == 0) {
        #pragma unroll
        for (int o = 16; o; o >>= 1) r += __shfl_down_sync(0xffffffffu, r, o);
        if (lane == 0) sh[0] = r;
    }
    __syncthreads();
    float out = sh[0];
    __syncthreads();
    return out;
}

// w[d] = sum_j bq[j] * Wk[j,d]
__global__ __launch_bounds__(256) void w_kernel(const float* __restrict__ Wk,
                                                const float* __restrict__ bq) {
    int d = blockIdx.x, t = threadIdx.x;
    float s = 0.f;
    for (int j = t; j < DD; j += 256) s += bq[j] * Wk[(size_t)j * DD + d];
    s = blockReduceSum(s);
    if (t == 0) g_w[d] = s;
}

// LayerNorm -> bf16, plus c_row = xn_row . w
__global__ __launch_bounds__(256) void ln_kernel(const float* __restrict__ x,
                                                 const float* __restrict__ g,
                                                 const float* __restrict__ b) {
    int row = blockIdx.x, t = threadIdx.x;
    const float* xr = x + (size_t)row * DD;
    float v[3];
    #pragma unroll
    for (int i = 0; i < 3; i++) v[i] = xr[t + i * 256];
    float mean = blockReduceSum(v[0] + v[1] + v[2]) * (1.0f / DD);
    float q = 0.f;
    #pragma unroll
    for (int i = 0; i < 3; i++) { float d = v[i] - mean; q += d * d; }
    float inv = rsqrtf(blockReduceSum(q) * (1.0f / DD) + 1e-5f);
    __nv_bfloat16* o = g_xn + (size_t)row * DD;
    float cdot = 0.f;
    #pragma unroll
    for (int i = 0; i < 3; i++) {
        int c = t + i * 256;
        float xv = (v[i] - mean) * inv * g[c] + b[c];
        o[c] = __float2bfloat16_rn(xv);
        cdot += xv * g_w[c];
    }
    cdot = blockReduceSum(cdot);
    if (t == 0) g_c[row] = cdot;
}

// Transpose W fp32 [m][i] -> bf16 [i][m] for both weights
__global__ __launch_bounds__(256) void convwT_kernel(const float* __restrict__ Wq,
                                                     const float* __restrict__ Wk) {
    __shared__ float tq[32][33];
    __shared__ float tk[32][33];
    int m0 = blockIdx.x * 32, i0 = blockIdx.y * 32;
    int tx = threadIdx.x & 31, ty = threadIdx.x >> 5;
    #pragma unroll
    for (int r = 0; r < 4; r++) {
        tq[ty + r * 8][tx] = Wq[(size_t)(m0 + ty + r * 8) * DD + i0 + tx];
        tk[ty + r * 8][tx] = Wk[(size_t)(m0 + ty + r * 8) * DD + i0 + tx];
    }
    __syncthreads();
    #pragma unroll
    for (int r = 0; r < 4; r++) {
        g_wqT[(size_t)(i0 + ty + r * 8) * DD + m0 + tx] = __float2bfloat16_rn(tq[tx][ty + r * 8]);
        g_wkT[(size_t)(i0 + ty + r * 8) * DD + m0 + tx] = __float2bfloat16_rn(tk[tx][ty + r * 8]);
    }
}

// x [b][s][d] fp32 -> g_xt [b][d][s] bf16 (R8-proven scalar version)
__global__ __launch_bounds__(256) void transpose_kernel(const float* __restrict__ x) {
    __shared__ float t[32][33];
    int b = blockIdx.z;
    int s0 = blockIdx.x * 32, d0 = blockIdx.y * 32;
    int tx = threadIdx.x & 31, ty = threadIdx.x >> 5;
    #pragma unroll
    for (int i = 0; i < 4; i++)
        t[ty + i * 8][tx] = x[(size_t)b * SS * DD + (size_t)(s0 + ty + i * 8) * DD + d0 + tx];
    __syncthreads();
    #pragma unroll
    for (int i = 0; i < 4; i++)
        g_xt[(size_t)b * DD * SS + (size_t)(d0 + ty + i * 8) * SS + s0 + tx] =
            __float2bfloat16_rn(t[tx][ty + i * 8]);
}

// g_si[row] = 1 / sum_{ntile} g_ps[row][ntile]
__global__ __launch_bounds__(256) void rowsum_kernel() {
    int r = blockIdx.x * 256 + threadIdx.x;
    const float4* ps = (const float4*)(g_ps + (size_t)r * 16);
    float4 a = ps[0], b = ps[1], c = ps[2], d = ps[3];
    float s = (a.x + a.y + a.z + a.w) + (b.x + b.y + b.z + b.w)
            + (c.x + c.y + c.z + c.w) + (d.x + d.y + d.z + d.w);
    g_si[r] = 1.0f / s;
}

// ---------------------------------------------------------------------------
extern "C" void kernel_launch(void* const* d_in, const int* in_sizes, int n_in,
                              void* d_out, int out_size) {
    const float* x    = (const float*)d_in[0];
    const float* ln_g = (const float*)d_in[1];
    const float* ln_b = (const float*)d_in[2];
    const float* Wq   = (const float*)d_in[3];
    const float* bq   = (const float*)d_in[4];
    const float* Wk   = (const float*)d_in[5];
    const float* bk   = (const float*)d_in[6];  (void)bk;
    float* out = (float*)d_out;

    const int SMEM_DYN = NSTAGE * STAGE_BYTES * 2;   // 61440
    cudaFuncSetAttribute(mma_gemm<0>, cudaFuncAttributeMaxDynamicSharedMemorySize, SMEM_DYN);
    cudaFuncSetAttribute(mma_gemm<1>, cudaFuncAttributeMaxDynamicSharedMemorySize, SMEM_DYN);
    cudaFuncSetAttribute(mma_gemm<2>, cudaFuncAttributeMaxDynamicSharedMemorySize, SMEM_DYN);

    __nv_bfloat16 *p_xn, *p_wqT, *p_wkT, *p_mt, *p_g, *p_pb, *p_xt;
    float* p_c;
    cudaGetSymbolAddress((void**)&p_xn,  g_xn);
    cudaGetSymbolAddress((void**)&p_wqT, g_wqT);
    cudaGetSymbolAddress((void**)&p_wkT, g_wkT);
    cudaGetSymbolAddress((void**)&p_mt,  g_mt);
    cudaGetSymbolAddress((void**)&p_g,   g_g);
    cudaGetSymbolAddress((void**)&p_pb,  g_pb);
    cudaGetSymbolAddress((void**)&p_xt,  g_xt);
    cudaGetSymbolAddress((void**)&p_c,   g_c);

    w_kernel<<<DD, 256>>>(Wk, bq);
    ln_kernel<<<MTOT, 256>>>(x, ln_g, ln_b);
    convwT_kernel<<<dim3(DD / 32, DD / 32), 256>>>(Wq, Wk);
    transpose_kernel<<<dim3(SS / 32, DD / 32, BB), 256>>>(x);

    // MT[j,i] = sum_m WkT[j,m] * WqT[i,m]  (= M[i,j], M = Wq^T Wk)
    mma_gemm<0><<<dim3(DD / 128, DD / 128, 1), 256, SMEM_DYN>>>(
        p_wkT, p_wqT, p_mt, nullptr, DD, DD, 0, 0, 0);

    // G = xn @ M   (M=16384, N=768, K=768)
    mma_gemm<0><<<dim3(DD / 128, MTOT / 128, 1), 256, SMEM_DYN>>>(
        p_xn, p_mt, p_g, nullptr, DD, DD, 0, 0, 0);

    // p_unnorm = exp(alpha*(G @ xn^T + c_t)) bf16, + per-row partial sums
    mma_gemm<1><<<dim3(SS / 128, SS / 128, BB), 256, SMEM_DYN>>>(
        p_g, p_xn, p_pb, p_c, SS, DD,
        (long)SS * DD, (long)SS * DD, (long)SS * SS);

    rowsum_kernel<<<MTOT / 256, 256>>>();

    // out = (P_un @ x) * inv_rowsum + x
    mma_gemm<2><<<dim3(DD / 128, SS / 128, BB), 256, SMEM_DYN>>>(
        p_pb, p_xt, out, x, DD, SS,
        (long)SS * SS, (long)DD * SS, (long)SS * DD);
}